// round 12
// baseline (speedup 1.0000x reference)
#include <cuda_runtime.h>
#include <cuda_fp16.h>
#include <cstdint>

#define DIM    768
#define SEQ    1024
#define BATCH  8
#define ROWS   (BATCH*SEQ)      /* 8192 */
#define HEADS  12
#define HD     64
#define HIDDEN 3072
#define LN_EPS 1e-6f

typedef __half hf;

/* ---------------- scratch (static device globals; no allocations) -------- */
__device__ __align__(16) hf    g_y  [ROWS * DIM];       /* LN out, fp16 */
__device__ __align__(16) hf    g_qkv[ROWS * 3 * DIM];   /* QKV, fp16 */
__device__ __align__(16) hf    g_att[ROWS * DIM];       /* attention out */
__device__ __align__(16) float g_x1 [ROWS * DIM];
__device__ __align__(16) hf    g_h  [ROWS * HIDDEN];    /* fc1 out */
/* transposed fp16 weights, [N][K] */
__device__ __align__(16) hf g_wq[3*DIM*DIM];
__device__ __align__(16) hf g_wp[DIM*DIM];
__device__ __align__(16) hf g_w1[HIDDEN*DIM];
__device__ __align__(16) hf g_w2[DIM*HIDDEN];

/* ---------------- helpers -------------------------------------------------- */
__device__ __forceinline__ float gelu_tanh(float u)
{
    return 0.5f * u * (1.0f + tanhf(0.7978845608028654f * (u + 0.044715f * u * u * u)));
}

__device__ __forceinline__ void mma16816(
    float& c0, float& c1, float& c2, float& c3,
    uint32_t a0, uint32_t a1, uint32_t a2, uint32_t a3,
    uint32_t b0, uint32_t b1)
{
    asm volatile(
        "mma.sync.aligned.m16n8k16.row.col.f32.f16.f16.f32 "
        "{%0,%1,%2,%3},{%4,%5,%6,%7},{%8,%9},{%0,%1,%2,%3};"
        : "+f"(c0), "+f"(c1), "+f"(c2), "+f"(c3)
        : "r"(a0), "r"(a1), "r"(a2), "r"(a3), "r"(b0), "r"(b1));
}

__device__ __forceinline__ uint32_t pack1(float x0, float x1)
{
    hf h0 = __float2half_rn(x0), h1 = __float2half_rn(x1);
    return ((uint32_t)__half_as_ushort(h1) << 16) | __half_as_ushort(h0);
}

__device__ __forceinline__ void cp16(uint32_t s, const void* g)
{
    asm volatile("cp.async.cg.shared.global [%0], [%1], 16;" :: "r"(s), "l"(g));
}
__device__ __forceinline__ void ldm_x4(uint32_t* r, uint32_t addr)
{
    asm volatile("ldmatrix.sync.aligned.m8n8.x4.shared.b16 {%0,%1,%2,%3}, [%4];"
        : "=r"(r[0]), "=r"(r[1]), "=r"(r[2]), "=r"(r[3]) : "r"(addr));
}

/* ---------------- merged weight transpose: 4 weights, one launch ----------- */
__global__ void __launch_bounds__(256) wt_all_kernel(
    const float* __restrict__ qkvw, const float* __restrict__ projw,
    const float* __restrict__ fc1w, const float* __restrict__ fc2w,
    hf* __restrict__ wq, hf* __restrict__ wp,
    hf* __restrict__ w1, hf* __restrict__ w2)
{
    int id = blockIdx.x;
    const float* W; hf* T; int K, N, tile;
    if (id < 1728)      { W = qkvw; T = wq; K = DIM;    N = 3*DIM;  tile = id; }
    else if (id < 2304) { W = projw; T = wp; K = DIM;   N = DIM;    tile = id - 1728; }
    else if (id < 4608) { W = fc1w; T = w1; K = DIM;    N = HIDDEN; tile = id - 2304; }
    else                { W = fc2w; T = w2; K = HIDDEN; N = DIM;    tile = id - 4608; }
    int nx = N >> 5;
    int n0 = (tile % nx) << 5, k0 = (tile / nx) << 5;

    __shared__ float s[32][33];
    int tx = threadIdx.x, ty = threadIdx.y;
    #pragma unroll
    for (int j = 0; j < 4; j++)
        s[ty + j*8][tx] = W[(long)(k0 + ty + j*8) * N + n0 + tx];
    __syncthreads();
    #pragma unroll
    for (int j = 0; j < 4; j++) {
        long o = (long)(n0 + ty + j*8) * K + k0 + tx;
        T[o] = __float2half_rn(s[tx][ty + j*8]);
    }
}

/* ---------------- layernorm -> single fp16 --------------------------------- */
__global__ void __launch_bounds__(256) ln_kernel(
    const float* __restrict__ x, const float* __restrict__ sc,
    const float* __restrict__ bi, hf* __restrict__ y)
{
    long row = blockIdx.x;
    int  t   = threadIdx.x;
    const float* xr = x + row * DIM;
    float v0 = xr[t], v1 = xr[t + 256], v2 = xr[t + 512];

    __shared__ float sbuf[8];
    __shared__ float s_mu, s_r;

    float s = v0 + v1 + v2;
    #pragma unroll
    for (int o = 16; o > 0; o >>= 1) s += __shfl_xor_sync(0xffffffffu, s, o);
    if ((t & 31) == 0) sbuf[t >> 5] = s;
    __syncthreads();
    if (t < 8) {
        float r = sbuf[t];
        #pragma unroll
        for (int o = 4; o > 0; o >>= 1) r += __shfl_xor_sync(0xffu, r, o);
        if (t == 0) s_mu = r * (1.0f / DIM);
    }
    __syncthreads();
    float mu = s_mu;
    float d0 = v0 - mu, d1 = v1 - mu, d2 = v2 - mu;
    float q = d0*d0 + d1*d1 + d2*d2;
    #pragma unroll
    for (int o = 16; o > 0; o >>= 1) q += __shfl_xor_sync(0xffffffffu, q, o);
    if ((t & 31) == 0) sbuf[t >> 5] = q;
    __syncthreads();
    if (t < 8) {
        float r = sbuf[t];
        #pragma unroll
        for (int o = 4; o > 0; o >>= 1) r += __shfl_xor_sync(0xffu, r, o);
        if (t == 0) s_r = rsqrtf(r * (1.0f / DIM) + LN_EPS);
    }
    __syncthreads();
    float rs = s_r;
    long base = row * DIM;
    y[base + t      ] = __float2half_rn(d0 * rs * sc[t      ] + bi[t      ]);
    y[base + t + 256] = __float2half_rn(d1 * rs * sc[t + 256] + bi[t + 256]);
    y[base + t + 512] = __float2half_rn(d2 * rs * sc[t + 512] + bi[t + 512]);
}

/* ================= flash attention: 8 warps x 16 q-rows ====================
 * BQ=128, 256 threads. Per-warp state halves vs 4-warp version -> 2 CTAs/SM
 * at ~2x warp occupancy. Identical per-row arithmetic (bit-identical output).
 */
#define BQ  128
#define BKV 64
#define QST 72
#define SQ_ELE (BQ*QST)
#define SK_ELE (BKV*QST)
#define FA_SMEM ((SQ_ELE + 2*SK_ELE + SK_ELE) * 2)   /* 46080 B */

__global__ void __launch_bounds__(256, 2) flash_kernel(
    const hf* __restrict__ qkv, hf* __restrict__ att)
{
    extern __shared__ hf sm[];
    hf* Qs  = sm;
    hf* Ks0 = Qs + SQ_ELE;
    hf* Vs  = Ks0 + 2*SK_ELE;
    uint32_t* VW = reinterpret_cast<uint32_t*>(Vs);
    uint32_t sQ, sK0;
    {
        uint32_t base = (uint32_t)__cvta_generic_to_shared(sm);
        sQ = base; sK0 = base + SQ_ELE*2;
    }

    int t = threadIdx.x, lane = t & 31, wid = t >> 5;     /* wid 0..7 */
    int gid = lane >> 2, tig = lane & 3;
    int bh = blockIdx.y, b = bh / HEADS, h = bh % HEADS;
    int q0 = blockIdx.x * BQ;

    const hf* Qp = qkv + ((long)b * SEQ + q0) * (3*DIM) + h * HD;
    const hf* Kp = qkv + (long)b * SEQ * (3*DIM) + DIM     + h * HD;
    const hf* Vp = qkv + (long)b * SEQ * (3*DIM) + 2*DIM   + h * HD;

    auto issueQ = [&]() {
        #pragma unroll
        for (int i = 0; i < 4; i++) {
            int g = t + i * 256;
            int row = g >> 3, c = g & 7;
            cp16(sQ + (row*QST + c*8)*2, Qp + (long)row*(3*DIM) + c*8);
        }
    };
    auto issueK = [&](int it) {
        uint32_t kb = sK0 + (it & 1) * (SK_ELE*2);
        #pragma unroll
        for (int i = 0; i < 2; i++) {
            int g = t + i * 256;
            int row = g >> 3, c = g & 7;
            cp16(kb + (row*QST + c*8)*2, Kp + (long)(it*BKV + row)*(3*DIM) + c*8);
        }
        asm volatile("cp.async.commit_group;");
    };

    /* V loader: row pair (2vrp, 2vrp+1), cols vdb..vdb+7 */
    int vrp = t & 31, vdb = (t >> 5) * 8;
    uint32_t va[4], vb[4];
    auto loadV = [&](int it) {
        const hf* p0 = Vp + (long)(it * BKV + 2*vrp) * (3*DIM) + vdb;
        const hf* p1 = p0 + 3*DIM;
        uint4 a0 = *reinterpret_cast<const uint4*>(p0);
        uint4 b0 = *reinterpret_cast<const uint4*>(p1);
        va[0]=a0.x; va[1]=a0.y; va[2]=a0.z; va[3]=a0.w;
        vb[0]=b0.x; vb[1]=b0.y; vb[2]=b0.z; vb[3]=b0.w;
    };

    issueQ();
    issueK(0);
    loadV(0);

    float acc[8][4];
    float oacc[8][4];
    float mrow[2], lrow[2];
    mrow[0] = mrow[1] = -1e30f;
    lrow[0] = lrow[1] = 0.0f;
    #pragma unroll
    for (int j = 0; j < 8; j++)
        #pragma unroll
        for (int r = 0; r < 4; r++) oacc[j][r] = 0.0f;

    int wm = wid * 16;

    for (int it = 0; it < SEQ / BKV; it++) {
        asm volatile("cp.async.wait_group 0;");
        __syncthreads();
        hf* Ks = Ks0 + (it & 1) * SK_ELE;

        #pragma unroll
        for (int j = 0; j < 8; j++)
            #pragma unroll
            for (int r = 0; r < 4; r++) acc[j][r] = 0.0f;

        /* S = Q @ K^T */
        #pragma unroll
        for (int ks = 0; ks < 4; ks++) {
            int row = wm + gid;
            uint32_t qa0 = *reinterpret_cast<const uint32_t*>(&Qs[ row    *QST + ks*16 + tig*2    ]);
            uint32_t qa1 = *reinterpret_cast<const uint32_t*>(&Qs[(row+8)*QST + ks*16 + tig*2    ]);
            uint32_t qa2 = *reinterpret_cast<const uint32_t*>(&Qs[ row    *QST + ks*16 + tig*2 + 8]);
            uint32_t qa3 = *reinterpret_cast<const uint32_t*>(&Qs[(row+8)*QST + ks*16 + tig*2 + 8]);
            #pragma unroll
            for (int tn = 0; tn < 8; tn++) {
                int nr = tn*8 + gid;
                uint32_t b0 = *reinterpret_cast<const uint32_t*>(&Ks[nr*QST + ks*16 + tig*2    ]);
                uint32_t b1 = *reinterpret_cast<const uint32_t*>(&Ks[nr*QST + ks*16 + tig*2 + 8]);
                float* c = acc[tn];
                mma16816(c[0],c[1],c[2],c[3], qa0,qa1,qa2,qa3, b0,b1);
            }
        }

        /* scale + online softmax update */
        {
            float mx0 = -1e30f, mx1 = -1e30f;
            #pragma unroll
            for (int tn = 0; tn < 8; tn++) {
                float* c = acc[tn];
                c[0] *= 0.125f; c[1] *= 0.125f; c[2] *= 0.125f; c[3] *= 0.125f;
                mx0 = fmaxf(mx0, fmaxf(c[0], c[1]));
                mx1 = fmaxf(mx1, fmaxf(c[2], c[3]));
            }
            #pragma unroll
            for (int o = 1; o <= 2; o <<= 1) {
                mx0 = fmaxf(mx0, __shfl_xor_sync(0xffffffffu, mx0, o));
                mx1 = fmaxf(mx1, __shfl_xor_sync(0xffffffffu, mx1, o));
            }
            float mn0 = fmaxf(mrow[0], mx0);
            float mn1 = fmaxf(mrow[1], mx1);
            float sc0 = __expf(mrow[0] - mn0);
            float sc1 = __expf(mrow[1] - mn1);
            float ls0 = 0.0f, ls1 = 0.0f;
            #pragma unroll
            for (int tn = 0; tn < 8; tn++) {
                float* c = acc[tn];
                c[0] = __expf(c[0] - mn0);
                c[1] = __expf(c[1] - mn0);
                c[2] = __expf(c[2] - mn1);
                c[3] = __expf(c[3] - mn1);
                ls0 += c[0] + c[1];
                ls1 += c[2] + c[3];
            }
            #pragma unroll
            for (int o = 1; o <= 2; o <<= 1) {
                ls0 += __shfl_xor_sync(0xffffffffu, ls0, o);
                ls1 += __shfl_xor_sync(0xffffffffu, ls1, o);
            }
            lrow[0] = lrow[0] * sc0 + ls0;
            lrow[1] = lrow[1] * sc1 + ls1;
            mrow[0] = mn0;
            mrow[1] = mn1;
            #pragma unroll
            for (int to = 0; to < 8; to++) {
                oacc[to][0] *= sc0; oacc[to][1] *= sc0;
                oacc[to][2] *= sc1; oacc[to][3] *= sc1;
            }
        }

        /* store V tile transposed (pair-pack via prmt) */
        #pragma unroll
        for (int k = 0; k < 4; k++) {
            VW[(vdb + 2*k    ) * (QST/2) + vrp] = __byte_perm(va[k], vb[k], 0x5410);
            VW[(vdb + 2*k + 1) * (QST/2) + vrp] = __byte_perm(va[k], vb[k], 0x7632);
        }
        if (it + 1 < SEQ / BKV) {
            issueK(it + 1);
            loadV(it + 1);
        }
        __syncthreads();

        /* O += P @ V  (P fp16) */
        #pragma unroll
        for (int j = 0; j < 4; j++) {
            uint32_t p0 = pack1(acc[2*j  ][0], acc[2*j  ][1]);
            uint32_t p1 = pack1(acc[2*j  ][2], acc[2*j  ][3]);
            uint32_t p2 = pack1(acc[2*j+1][0], acc[2*j+1][1]);
            uint32_t p3 = pack1(acc[2*j+1][2], acc[2*j+1][3]);
            #pragma unroll
            for (int to = 0; to < 8; to++) {
                int d = to*8 + gid;
                uint32_t b0 = *reinterpret_cast<const uint32_t*>(&Vs[d*QST + j*16 + tig*2    ]);
                uint32_t b1 = *reinterpret_cast<const uint32_t*>(&Vs[d*QST + j*16 + tig*2 + 8]);
                float* c = oacc[to];
                mma16816(c[0],c[1],c[2],c[3], p0,p1,p2,p3, b0,b1);
            }
        }
    }

    /* epilogue: O / l -> att (single fp16) */
    uint32_t* AW = reinterpret_cast<uint32_t*>(att);
    {
        float inv0 = 1.0f / lrow[0];
        float inv1 = 1.0f / lrow[1];
        int row = q0 + wm + gid;
        #pragma unroll
        for (int to = 0; to < 8; to++) {
            int col = h*HD + to*8 + tig*2;
            float* c = oacc[to];
            long o0 = (((long)b*SEQ + row    ) * DIM + col) >> 1;
            long o1 = (((long)b*SEQ + row + 8) * DIM + col) >> 1;
            AW[o0] = pack1(c[0]*inv0, c[1]*inv0);
            AW[o1] = pack1(c[2]*inv1, c[3]*inv1);
        }
    }
}

/* ================= dense GEMM: pure fp16, templated BM ===================== */
#define BN  128
#define BK2 32
#define SEB 40

template <int BMT>
__global__ void __launch_bounds__(BMT*2, (BMT==128)?2:3) gemm_hf(
    const hf* __restrict__ Ag, const hf* __restrict__ Bg,
    const float* __restrict__ bias, const float* __restrict__ Rsd,
    float* __restrict__ Cf, hf* __restrict__ Ch, int doGelu,
    int M, int N, int K)
{
    constexpr int TSZA = BMT * SEB;
    constexpr int TSZB = BN  * SEB;
    extern __shared__ hf gsm[];
    uint32_t sbase = (uint32_t)__cvta_generic_to_shared(gsm);

    int m0 = blockIdx.y * BMT;
    int n0 = blockIdx.x * BN;
    int t  = threadIdx.x;
    int lane = t & 31, wid = t >> 5;
    int gid = lane >> 2, tig = lane & 3;
    int warp_m = (BMT == 128) ? ((wid >> 2) << 6) : 0;
    int warp_n = (wid & 3) << 5;

    int r0c = t >> 2, c0c = (t & 3) * 8;

    auto issue = [&](int st) {
        int buf = st & 3;
        long k0 = (long)st * BK2;
        uint32_t dA = sbase + (buf*TSZA)*2;
        uint32_t dB = sbase + (4*TSZA + buf*TSZB)*2;
        cp16(dA + ( r0c        *SEB + c0c)*2, Ag + (long)(m0 + r0c        )*K + k0 + c0c);
        cp16(dA + ((r0c+BMT/2) *SEB + c0c)*2, Ag + (long)(m0 + r0c + BMT/2)*K + k0 + c0c);
        if (BMT == 128) {
            cp16(dB + ( r0c    *SEB + c0c)*2, Bg + (long)(n0 + r0c     )*K + k0 + c0c);
            cp16(dB + ((r0c+64)*SEB + c0c)*2, Bg + (long)(n0 + r0c + 64)*K + k0 + c0c);
        } else {
            #pragma unroll
            for (int p = 0; p < 4; p++)
                cp16(dB + ((r0c + p*32)*SEB + c0c)*2,
                     Bg + (long)(n0 + r0c + p*32)*K + k0 + c0c);
        }
        asm volatile("cp.async.commit_group;");
    };

    float acc[4][4][4];
    #pragma unroll
    for (int i = 0; i < 4; i++)
        #pragma unroll
        for (int j = 0; j < 4; j++)
            #pragma unroll
            for (int r = 0; r < 4; r++) acc[i][j][r] = 0.0f;

    int t4 = lane >> 3, li = lane & 7;
    int a_row = (t4 & 1) * 8 + li,  a_col = (t4 >> 1) * 8;
    int b_row = (t4 >> 1) * 8 + li, b_col = (t4 & 1) * 8;

    int kt = K / BK2;
    issue(0); issue(1); issue(2);

    for (int kk = 0; kk < kt; kk++) {
        int rem = kt - 1 - kk;
        if (rem >= 2)      asm volatile("cp.async.wait_group 2;");
        else if (rem == 1) asm volatile("cp.async.wait_group 1;");
        else               asm volatile("cp.async.wait_group 0;");
        __syncthreads();
        if (kk + 3 < kt) issue(kk + 3);

        int buf = kk & 3;
        uint32_t sA = sbase + (buf*TSZA)*2;
        uint32_t sB = sbase + (4*TSZA + buf*TSZB)*2;

        #pragma unroll
        for (int ks = 0; ks < 2; ks++) {
            int kc = ks * 16;
            uint32_t a[4][4], bb2[2][4];
            #pragma unroll
            for (int tm = 0; tm < 4; tm++)
                ldm_x4(a[tm], sA + ((warp_m + tm*16 + a_row)*SEB + kc + a_col)*2);
            #pragma unroll
            for (int p = 0; p < 2; p++)
                ldm_x4(bb2[p], sB + ((warp_n + p*16 + b_row)*SEB + kc + b_col)*2);

            #pragma unroll
            for (int tm = 0; tm < 4; tm++)
                #pragma unroll
                for (int tn = 0; tn < 4; tn++) {
                    float* c = acc[tm][tn];
                    uint32_t* bb = bb2[tn >> 1];
                    mma16816(c[0],c[1],c[2],c[3],
                             a[tm][0],a[tm][1],a[tm][2],a[tm][3],
                             bb[(tn&1)*2], bb[(tn&1)*2+1]);
                }
        }
    }

    /* epilogue */
    #pragma unroll
    for (int tn = 0; tn < 4; tn++) {
        int col = n0 + warp_n + tn * 8 + tig * 2;
        float b0 = bias ? bias[col]     : 0.0f;
        float b1 = bias ? bias[col + 1] : 0.0f;
        #pragma unroll
        for (int tm = 0; tm < 4; tm++) {
            int row0 = m0 + warp_m + tm * 16 + gid;
            float* c = acc[tm][tn];
            #pragma unroll
            for (int half = 0; half < 2; half++) {
                int row = row0 + half * 8;
                float v0 = c[half*2 + 0] + b0;
                float v1 = c[half*2 + 1] + b1;
                long off = (long)row * N + col;
                if (Ch) {
                    if (doGelu) { v0 = gelu_tanh(v0); v1 = gelu_tanh(v1); }
                    reinterpret_cast<uint32_t*>(Ch)[off >> 1] = pack1(v0, v1);
                } else {
                    if (Rsd) {
                        float2 r = *reinterpret_cast<const float2*>(Rsd + off);
                        v0 += r.x; v1 += r.y;
                    }
                    *reinterpret_cast<float2*>(Cf + off) = make_float2(v0, v1);
                }
            }
        }
    }
}

#define GEMM_SMEM_128 (4*(128+128)*SEB*2)   /* 81920 */
#define GEMM_SMEM_64  (4*( 64+128)*SEB*2)   /* 61440 */

/* ---------------- launch --------------------------------------------------- */
extern "C" void kernel_launch(void* const* d_in, const int* in_sizes, int n_in,
                              void* d_out, int out_size)
{
    const float* x     = (const float*)d_in[0];
    const float* ln1s  = (const float*)d_in[1];
    const float* ln1b  = (const float*)d_in[2];
    const float* qkvw  = (const float*)d_in[3];
    const float* qkvb  = (const float*)d_in[4];
    const float* projw = (const float*)d_in[5];
    const float* projb = (const float*)d_in[6];
    const float* ln2s  = (const float*)d_in[7];
    const float* ln2b  = (const float*)d_in[8];
    const float* fc1w  = (const float*)d_in[9];
    const float* fc1b  = (const float*)d_in[10];
    const float* fc2w  = (const float*)d_in[11];
    const float* fc2b  = (const float*)d_in[12];
    float* out = (float*)d_out;

    hf *y, *qkvh, *att, *hb, *wq, *wp, *w1, *w2;
    float *x1;
    cudaGetSymbolAddress((void**)&y,    g_y);
    cudaGetSymbolAddress((void**)&qkvh, g_qkv);
    cudaGetSymbolAddress((void**)&att,  g_att);
    cudaGetSymbolAddress((void**)&x1,   g_x1);
    cudaGetSymbolAddress((void**)&hb,   g_h);
    cudaGetSymbolAddress((void**)&wq,   g_wq);
    cudaGetSymbolAddress((void**)&wp,   g_wp);
    cudaGetSymbolAddress((void**)&w1,   g_w1);
    cudaGetSymbolAddress((void**)&w2,   g_w2);

    cudaFuncSetAttribute(flash_kernel,
        cudaFuncAttributeMaxDynamicSharedMemorySize, FA_SMEM);
    cudaFuncSetAttribute(gemm_hf<128>,
        cudaFuncAttributeMaxDynamicSharedMemorySize, GEMM_SMEM_128);
    cudaFuncSetAttribute(gemm_hf<64>,
        cudaFuncAttributeMaxDynamicSharedMemorySize, GEMM_SMEM_64);

    /* 0. all weight transposes, one launch */
    wt_all_kernel<<<6912, dim3(32,8)>>>(qkvw, projw, fc1w, fc2w, wq, wp, w1, w2);

    /* 1. LN1 -> y fp16 */
    ln_kernel<<<ROWS, 256>>>(x, ln1s, ln1b, y);

    /* 2. QKV = y @ Wq + b  (fp16 out) */
    gemm_hf<128><<<dim3(3*DIM/BN, ROWS/128), 256, GEMM_SMEM_128>>>(
        y, wq, qkvb, nullptr, nullptr, qkvh, 0,
        ROWS, 3*DIM, DIM);

    /* 3-5. flash attention -> att fp16 (8 warps) */
    flash_kernel<<<dim3(SEQ / BQ, BATCH * HEADS), 256, FA_SMEM>>>(qkvh, att);

    /* 6. x1 = att @ Wp + b + x  (f32 out) */
    gemm_hf<64><<<dim3(DIM/BN, ROWS/64), 128, GEMM_SMEM_64>>>(
        att, wp, projb, x, x1, nullptr, 0,
        ROWS, DIM, DIM);

    /* 7. LN2 -> y fp16 */
    ln_kernel<<<ROWS, 256>>>(x1, ln2s, ln2b, y);

    /* 8. h = gelu(y @ W1 + b)  (fp16 out) */
    gemm_hf<128><<<dim3(HIDDEN/BN, ROWS/128), 256, GEMM_SMEM_128>>>(
        y, w1, fc1b, nullptr, nullptr, hb, 1,
        ROWS, HIDDEN, DIM);

    /* 9. out = h @ W2 + b + x1  (f32 out) */
    gemm_hf<64><<<dim3(DIM/BN, ROWS/64), 128, GEMM_SMEM_64>>>(
        hb, w2, fc2b, x1, out, nullptr, 0,
        ROWS, DIM, HIDDEN);
}

// round 13
// speedup vs baseline: 1.0478x; 1.0478x over previous
#include <cuda_runtime.h>
#include <cuda_fp16.h>
#include <cstdint>

#define DIM    768
#define SEQ    1024
#define BATCH  8
#define ROWS   (BATCH*SEQ)      /* 8192 */
#define HEADS  12
#define HD     64
#define HIDDEN 3072
#define LN_EPS 1e-6f

typedef __half hf;

/* ---------------- scratch (static device globals; no allocations) -------- */
__device__ __align__(16) hf    g_y  [ROWS * DIM];       /* LN out, fp16 */
__device__ __align__(16) hf    g_qkv[ROWS * 3 * DIM];   /* QKV, fp16 */
__device__ __align__(16) hf    g_att[ROWS * DIM];       /* attention out */
__device__ __align__(16) float g_x1 [ROWS * DIM];
__device__ __align__(16) hf    g_h  [ROWS * HIDDEN];    /* fc1 out */
/* transposed fp16 weights, [N][K] */
__device__ __align__(16) hf g_wq[3*DIM*DIM];
__device__ __align__(16) hf g_wp[DIM*DIM];
__device__ __align__(16) hf g_w1[HIDDEN*DIM];
__device__ __align__(16) hf g_w2[DIM*HIDDEN];

/* ---------------- helpers -------------------------------------------------- */
__device__ __forceinline__ float gelu_tanh(float u)
{
    return 0.5f * u * (1.0f + tanhf(0.7978845608028654f * (u + 0.044715f * u * u * u)));
}

__device__ __forceinline__ void mma16816(
    float& c0, float& c1, float& c2, float& c3,
    uint32_t a0, uint32_t a1, uint32_t a2, uint32_t a3,
    uint32_t b0, uint32_t b1)
{
    asm volatile(
        "mma.sync.aligned.m16n8k16.row.col.f32.f16.f16.f32 "
        "{%0,%1,%2,%3},{%4,%5,%6,%7},{%8,%9},{%0,%1,%2,%3};"
        : "+f"(c0), "+f"(c1), "+f"(c2), "+f"(c3)
        : "r"(a0), "r"(a1), "r"(a2), "r"(a3), "r"(b0), "r"(b1));
}

__device__ __forceinline__ uint32_t pack1(float x0, float x1)
{
    hf h0 = __float2half_rn(x0), h1 = __float2half_rn(x1);
    return ((uint32_t)__half_as_ushort(h1) << 16) | __half_as_ushort(h0);
}

__device__ __forceinline__ void cp16(uint32_t s, const void* g)
{
    asm volatile("cp.async.cg.shared.global [%0], [%1], 16;" :: "r"(s), "l"(g));
}
__device__ __forceinline__ void ldm_x4(uint32_t* r, uint32_t addr)
{
    asm volatile("ldmatrix.sync.aligned.m8n8.x4.shared.b16 {%0,%1,%2,%3}, [%4];"
        : "=r"(r[0]), "=r"(r[1]), "=r"(r[2]), "=r"(r[3]) : "r"(addr));
}

/* ---------------- merged weight transpose: 4 weights, one launch ----------- */
__global__ void __launch_bounds__(256) wt_all_kernel(
    const float* __restrict__ qkvw, const float* __restrict__ projw,
    const float* __restrict__ fc1w, const float* __restrict__ fc2w,
    hf* __restrict__ wq, hf* __restrict__ wp,
    hf* __restrict__ w1, hf* __restrict__ w2)
{
    int id = blockIdx.x;
    const float* W; hf* T; int K, N, tile;
    if (id < 1728)      { W = qkvw; T = wq; K = DIM;    N = 3*DIM;  tile = id; }
    else if (id < 2304) { W = projw; T = wp; K = DIM;   N = DIM;    tile = id - 1728; }
    else if (id < 4608) { W = fc1w; T = w1; K = DIM;    N = HIDDEN; tile = id - 2304; }
    else                { W = fc2w; T = w2; K = HIDDEN; N = DIM;    tile = id - 4608; }
    int nx = N >> 5;
    int n0 = (tile % nx) << 5, k0 = (tile / nx) << 5;

    __shared__ float s[32][33];
    int tx = threadIdx.x, ty = threadIdx.y;
    #pragma unroll
    for (int j = 0; j < 4; j++)
        s[ty + j*8][tx] = W[(long)(k0 + ty + j*8) * N + n0 + tx];
    __syncthreads();
    #pragma unroll
    for (int j = 0; j < 4; j++) {
        long o = (long)(n0 + ty + j*8) * K + k0 + tx;
        T[o] = __float2half_rn(s[tx][ty + j*8]);
    }
}

/* ---------------- layernorm -> single fp16 --------------------------------- */
__global__ void __launch_bounds__(256) ln_kernel(
    const float* __restrict__ x, const float* __restrict__ sc,
    const float* __restrict__ bi, hf* __restrict__ y)
{
    long row = blockIdx.x;
    int  t   = threadIdx.x;
    const float* xr = x + row * DIM;
    float v0 = xr[t], v1 = xr[t + 256], v2 = xr[t + 512];

    __shared__ float sbuf[8];
    __shared__ float s_mu, s_r;

    float s = v0 + v1 + v2;
    #pragma unroll
    for (int o = 16; o > 0; o >>= 1) s += __shfl_xor_sync(0xffffffffu, s, o);
    if ((t & 31) == 0) sbuf[t >> 5] = s;
    __syncthreads();
    if (t < 8) {
        float r = sbuf[t];
        #pragma unroll
        for (int o = 4; o > 0; o >>= 1) r += __shfl_xor_sync(0xffu, r, o);
        if (t == 0) s_mu = r * (1.0f / DIM);
    }
    __syncthreads();
    float mu = s_mu;
    float d0 = v0 - mu, d1 = v1 - mu, d2 = v2 - mu;
    float q = d0*d0 + d1*d1 + d2*d2;
    #pragma unroll
    for (int o = 16; o > 0; o >>= 1) q += __shfl_xor_sync(0xffffffffu, q, o);
    if ((t & 31) == 0) sbuf[t >> 5] = q;
    __syncthreads();
    if (t < 8) {
        float r = sbuf[t];
        #pragma unroll
        for (int o = 4; o > 0; o >>= 1) r += __shfl_xor_sync(0xffu, r, o);
        if (t == 0) s_r = rsqrtf(r * (1.0f / DIM) + LN_EPS);
    }
    __syncthreads();
    float rs = s_r;
    long base = row * DIM;
    y[base + t      ] = __float2half_rn(d0 * rs * sc[t      ] + bi[t      ]);
    y[base + t + 256] = __float2half_rn(d1 * rs * sc[t + 256] + bi[t + 256]);
    y[base + t + 512] = __float2half_rn(d2 * rs * sc[t + 512] + bi[t + 512]);
}

/* ================= flash attention: 4 warps x 32 q-rows, ldmatrix loads ====
 * R10 shape (best measured) with all fragment LDS replaced by ldmatrix.x4:
 * per ks-step 6 ldm (vs 24 scalar LDS); per j-step 4 ldm (vs 16).
 * Identical fragments & mma order -> bit-identical output.
 */
#define BQ  128
#define BKV 64
#define QST 72
#define SQ_ELE (BQ*QST)
#define SK_ELE (BKV*QST)
#define FA_SMEM ((SQ_ELE + 2*SK_ELE + SK_ELE) * 2)   /* 46080 B */

__global__ void __launch_bounds__(128) flash_kernel(
    const hf* __restrict__ qkv, hf* __restrict__ att)
{
    extern __shared__ hf sm[];
    hf* Vs  = sm + SQ_ELE + 2*SK_ELE;
    uint32_t* VW = reinterpret_cast<uint32_t*>(Vs);
    uint32_t sQ, sK0, sV;
    {
        uint32_t base = (uint32_t)__cvta_generic_to_shared(sm);
        sQ = base; sK0 = base + SQ_ELE*2; sV = sK0 + 2*SK_ELE*2;
    }

    int t = threadIdx.x, lane = t & 31, wid = t >> 5;
    int gid = lane >> 2, tig = lane & 3;
    int t4 = lane >> 3, li = lane & 7;
    /* ldmatrix lane-address components (same mapping as dense GEMM) */
    int a_row = (t4 & 1) * 8 + li,  a_col = (t4 >> 1) * 8;   /* A fragments */
    int b_row = (t4 >> 1) * 8 + li, b_col = (t4 & 1) * 8;    /* B fragment pairs */

    int bh = blockIdx.y, b = bh / HEADS, h = bh % HEADS;
    int q0 = blockIdx.x * BQ;

    const hf* Qp = qkv + ((long)b * SEQ + q0) * (3*DIM) + h * HD;
    const hf* Kp = qkv + (long)b * SEQ * (3*DIM) + DIM     + h * HD;
    const hf* Vp = qkv + (long)b * SEQ * (3*DIM) + 2*DIM   + h * HD;

    auto issueQ = [&]() {
        #pragma unroll
        for (int i = 0; i < 8; i++) {
            int g = t + i * 128;
            int row = g >> 3, c = g & 7;
            cp16(sQ + (row*QST + c*8)*2, Qp + (long)row*(3*DIM) + c*8);
        }
    };
    auto issueK = [&](int it) {
        uint32_t kb = sK0 + (it & 1) * (SK_ELE*2);
        #pragma unroll
        for (int i = 0; i < 4; i++) {
            int g = t + i * 128;
            int row = g >> 3, c = g & 7;
            cp16(kb + (row*QST + c*8)*2, Kp + (long)(it*BKV + row)*(3*DIM) + c*8);
        }
        asm volatile("cp.async.commit_group;");
    };

    int vrp = t & 31, vdb = (t >> 5) * 16;
    uint32_t va[8], vb[8];
    auto loadV = [&](int it) {
        const hf* p0 = Vp + (long)(it * BKV + 2*vrp) * (3*DIM) + vdb;
        const hf* p1 = p0 + 3*DIM;
        uint4 a0 = *reinterpret_cast<const uint4*>(p0);
        uint4 a1 = *reinterpret_cast<const uint4*>(p0 + 8);
        uint4 b0 = *reinterpret_cast<const uint4*>(p1);
        uint4 b1 = *reinterpret_cast<const uint4*>(p1 + 8);
        va[0]=a0.x; va[1]=a0.y; va[2]=a0.z; va[3]=a0.w;
        va[4]=a1.x; va[5]=a1.y; va[6]=a1.z; va[7]=a1.w;
        vb[0]=b0.x; vb[1]=b0.y; vb[2]=b0.z; vb[3]=b0.w;
        vb[4]=b1.x; vb[5]=b1.y; vb[6]=b1.z; vb[7]=b1.w;
    };

    issueQ();
    issueK(0);
    loadV(0);

    float acc[2][8][4];
    float oacc[2][8][4];
    float mrow[2][2], lrow[2][2];
    #pragma unroll
    for (int i = 0; i < 2; i++) {
        mrow[i][0] = mrow[i][1] = -1e30f;
        lrow[i][0] = lrow[i][1] = 0.0f;
        #pragma unroll
        for (int j = 0; j < 8; j++)
            #pragma unroll
            for (int r = 0; r < 4; r++) oacc[i][j][r] = 0.0f;
    }

    int wm = wid * 32;

    for (int it = 0; it < SEQ / BKV; it++) {
        asm volatile("cp.async.wait_group 0;");
        __syncthreads();
        uint32_t sK = sK0 + (it & 1) * (SK_ELE*2);

        #pragma unroll
        for (int i = 0; i < 2; i++)
            #pragma unroll
            for (int j = 0; j < 8; j++)
                #pragma unroll
                for (int r = 0; r < 4; r++) acc[i][j][r] = 0.0f;

        /* S = Q @ K^T  (ldmatrix fragments) */
        #pragma unroll
        for (int ks = 0; ks < 4; ks++) {
            uint32_t qa[2][4], kb4[4][4];
            #pragma unroll
            for (int tm = 0; tm < 2; tm++)
                ldm_x4(qa[tm], sQ + ((wm + tm*16 + a_row)*QST + ks*16 + a_col)*2);
            #pragma unroll
            for (int p = 0; p < 4; p++)
                ldm_x4(kb4[p], sK + ((p*16 + b_row)*QST + ks*16 + b_col)*2);
            #pragma unroll
            for (int tn = 0; tn < 8; tn++) {
                uint32_t* kk = kb4[tn >> 1];
                uint32_t b0 = kk[(tn & 1) * 2], b1 = kk[(tn & 1) * 2 + 1];
                #pragma unroll
                for (int tm = 0; tm < 2; tm++) {
                    float* c = acc[tm][tn];
                    mma16816(c[0],c[1],c[2],c[3],
                             qa[tm][0],qa[tm][1],qa[tm][2],qa[tm][3], b0,b1);
                }
            }
        }

        /* scale + online softmax update */
        #pragma unroll
        for (int tm = 0; tm < 2; tm++) {
            float mx0 = -1e30f, mx1 = -1e30f;
            #pragma unroll
            for (int tn = 0; tn < 8; tn++) {
                float* c = acc[tm][tn];
                c[0] *= 0.125f; c[1] *= 0.125f; c[2] *= 0.125f; c[3] *= 0.125f;
                mx0 = fmaxf(mx0, fmaxf(c[0], c[1]));
                mx1 = fmaxf(mx1, fmaxf(c[2], c[3]));
            }
            #pragma unroll
            for (int o = 1; o <= 2; o <<= 1) {
                mx0 = fmaxf(mx0, __shfl_xor_sync(0xffffffffu, mx0, o));
                mx1 = fmaxf(mx1, __shfl_xor_sync(0xffffffffu, mx1, o));
            }
            float mn0 = fmaxf(mrow[tm][0], mx0);
            float mn1 = fmaxf(mrow[tm][1], mx1);
            float sc0 = __expf(mrow[tm][0] - mn0);
            float sc1 = __expf(mrow[tm][1] - mn1);
            float ls0 = 0.0f, ls1 = 0.0f;
            #pragma unroll
            for (int tn = 0; tn < 8; tn++) {
                float* c = acc[tm][tn];
                c[0] = __expf(c[0] - mn0);
                c[1] = __expf(c[1] - mn0);
                c[2] = __expf(c[2] - mn1);
                c[3] = __expf(c[3] - mn1);
                ls0 += c[0] + c[1];
                ls1 += c[2] + c[3];
            }
            #pragma unroll
            for (int o = 1; o <= 2; o <<= 1) {
                ls0 += __shfl_xor_sync(0xffffffffu, ls0, o);
                ls1 += __shfl_xor_sync(0xffffffffu, ls1, o);
            }
            lrow[tm][0] = lrow[tm][0] * sc0 + ls0;
            lrow[tm][1] = lrow[tm][1] * sc1 + ls1;
            mrow[tm][0] = mn0;
            mrow[tm][1] = mn1;
            #pragma unroll
            for (int to = 0; to < 8; to++) {
                oacc[tm][to][0] *= sc0; oacc[tm][to][1] *= sc0;
                oacc[tm][to][2] *= sc1; oacc[tm][to][3] *= sc1;
            }
        }

        /* store V tile transposed (pair-pack via prmt) */
        #pragma unroll
        for (int k = 0; k < 8; k++) {
            VW[(vdb + 2*k    ) * (QST/2) + vrp] = __byte_perm(va[k], vb[k], 0x5410);
            VW[(vdb + 2*k + 1) * (QST/2) + vrp] = __byte_perm(va[k], vb[k], 0x7632);
        }
        if (it + 1 < SEQ / BKV) {
            issueK(it + 1);
            loadV(it + 1);
        }
        __syncthreads();

        /* O += P @ V  (P fp16, V fragments via ldmatrix) */
        #pragma unroll
        for (int j = 0; j < 4; j++) {
            uint32_t pH[2][4];
            #pragma unroll
            for (int tm = 0; tm < 2; tm++) {
                pH[tm][0] = pack1(acc[tm][2*j  ][0], acc[tm][2*j  ][1]);
                pH[tm][1] = pack1(acc[tm][2*j  ][2], acc[tm][2*j  ][3]);
                pH[tm][2] = pack1(acc[tm][2*j+1][0], acc[tm][2*j+1][1]);
                pH[tm][3] = pack1(acc[tm][2*j+1][2], acc[tm][2*j+1][3]);
            }
            uint32_t vb4[4][4];
            #pragma unroll
            for (int p = 0; p < 4; p++)
                ldm_x4(vb4[p], sV + ((p*16 + b_row)*QST + j*16 + b_col)*2);
            #pragma unroll
            for (int to = 0; to < 8; to++) {
                uint32_t* vv = vb4[to >> 1];
                uint32_t b0 = vv[(to & 1) * 2], b1 = vv[(to & 1) * 2 + 1];
                #pragma unroll
                for (int tm = 0; tm < 2; tm++) {
                    float* c = oacc[tm][to];
                    mma16816(c[0],c[1],c[2],c[3],
                             pH[tm][0],pH[tm][1],pH[tm][2],pH[tm][3], b0,b1);
                }
            }
        }
    }

    /* epilogue: O / l -> att (single fp16) */
    uint32_t* AW = reinterpret_cast<uint32_t*>(att);
    #pragma unroll
    for (int tm = 0; tm < 2; tm++) {
        float inv0 = 1.0f / lrow[tm][0];
        float inv1 = 1.0f / lrow[tm][1];
        int row = q0 + wm + tm*16 + gid;
        #pragma unroll
        for (int to = 0; to < 8; to++) {
            int col = h*HD + to*8 + tig*2;
            float* c = oacc[tm][to];
            long o0 = (((long)b*SEQ + row    ) * DIM + col) >> 1;
            long o1 = (((long)b*SEQ + row + 8) * DIM + col) >> 1;
            AW[o0] = pack1(c[0]*inv0, c[1]*inv0);
            AW[o1] = pack1(c[2]*inv1, c[3]*inv1);
        }
    }
}

/* ================= dense GEMM: pure fp16, templated BM ===================== */
#define BN  128
#define BK2 32
#define SEB 40

template <int BMT>
__global__ void __launch_bounds__(BMT*2, (BMT==128)?2:3) gemm_hf(
    const hf* __restrict__ Ag, const hf* __restrict__ Bg,
    const float* __restrict__ bias, const float* __restrict__ Rsd,
    float* __restrict__ Cf, hf* __restrict__ Ch, int doGelu,
    int M, int N, int K)
{
    constexpr int TSZA = BMT * SEB;
    constexpr int TSZB = BN  * SEB;
    extern __shared__ hf gsm[];
    uint32_t sbase = (uint32_t)__cvta_generic_to_shared(gsm);

    int m0 = blockIdx.y * BMT;
    int n0 = blockIdx.x * BN;
    int t  = threadIdx.x;
    int lane = t & 31, wid = t >> 5;
    int gid = lane >> 2, tig = lane & 3;
    int warp_m = (BMT == 128) ? ((wid >> 2) << 6) : 0;
    int warp_n = (wid & 3) << 5;

    int r0c = t >> 2, c0c = (t & 3) * 8;

    auto issue = [&](int st) {
        int buf = st & 3;
        long k0 = (long)st * BK2;
        uint32_t dA = sbase + (buf*TSZA)*2;
        uint32_t dB = sbase + (4*TSZA + buf*TSZB)*2;
        cp16(dA + ( r0c        *SEB + c0c)*2, Ag + (long)(m0 + r0c        )*K + k0 + c0c);
        cp16(dA + ((r0c+BMT/2) *SEB + c0c)*2, Ag + (long)(m0 + r0c + BMT/2)*K + k0 + c0c);
        if (BMT == 128) {
            cp16(dB + ( r0c    *SEB + c0c)*2, Bg + (long)(n0 + r0c     )*K + k0 + c0c);
            cp16(dB + ((r0c+64)*SEB + c0c)*2, Bg + (long)(n0 + r0c + 64)*K + k0 + c0c);
        } else {
            #pragma unroll
            for (int p = 0; p < 4; p++)
                cp16(dB + ((r0c + p*32)*SEB + c0c)*2,
                     Bg + (long)(n0 + r0c + p*32)*K + k0 + c0c);
        }
        asm volatile("cp.async.commit_group;");
    };

    float acc[4][4][4];
    #pragma unroll
    for (int i = 0; i < 4; i++)
        #pragma unroll
        for (int j = 0; j < 4; j++)
            #pragma unroll
            for (int r = 0; r < 4; r++) acc[i][j][r] = 0.0f;

    int t4 = lane >> 3, li = lane & 7;
    int a_row = (t4 & 1) * 8 + li,  a_col = (t4 >> 1) * 8;
    int b_row = (t4 >> 1) * 8 + li, b_col = (t4 & 1) * 8;

    int kt = K / BK2;
    issue(0); issue(1); issue(2);

    for (int kk = 0; kk < kt; kk++) {
        int rem = kt - 1 - kk;
        if (rem >= 2)      asm volatile("cp.async.wait_group 2;");
        else if (rem == 1) asm volatile("cp.async.wait_group 1;");
        else               asm volatile("cp.async.wait_group 0;");
        __syncthreads();
        if (kk + 3 < kt) issue(kk + 3);

        int buf = kk & 3;
        uint32_t sA = sbase + (buf*TSZA)*2;
        uint32_t sB = sbase + (4*TSZA + buf*TSZB)*2;

        #pragma unroll
        for (int ks = 0; ks < 2; ks++) {
            int kc = ks * 16;
            uint32_t a[4][4], bb2[2][4];
            #pragma unroll
            for (int tm = 0; tm < 4; tm++)
                ldm_x4(a[tm], sA + ((warp_m + tm*16 + a_row)*SEB + kc + a_col)*2);
            #pragma unroll
            for (int p = 0; p < 2; p++)
                ldm_x4(bb2[p], sB + ((warp_n + p*16 + b_row)*SEB + kc + b_col)*2);

            #pragma unroll
            for (int tm = 0; tm < 4; tm++)
                #pragma unroll
                for (int tn = 0; tn < 4; tn++) {
                    float* c = acc[tm][tn];
                    uint32_t* bb = bb2[tn >> 1];
                    mma16816(c[0],c[1],c[2],c[3],
                             a[tm][0],a[tm][1],a[tm][2],a[tm][3],
                             bb[(tn&1)*2], bb[(tn&1)*2+1]);
                }
        }
    }

    /* epilogue */
    #pragma unroll
    for (int tn = 0; tn < 4; tn++) {
        int col = n0 + warp_n + tn * 8 + tig * 2;
        float b0 = bias ? bias[col]     : 0.0f;
        float b1 = bias ? bias[col + 1] : 0.0f;
        #pragma unroll
        for (int tm = 0; tm < 4; tm++) {
            int row0 = m0 + warp_m + tm * 16 + gid;
            float* c = acc[tm][tn];
            #pragma unroll
            for (int half = 0; half < 2; half++) {
                int row = row0 + half * 8;
                float v0 = c[half*2 + 0] + b0;
                float v1 = c[half*2 + 1] + b1;
                long off = (long)row * N + col;
                if (Ch) {
                    if (doGelu) { v0 = gelu_tanh(v0); v1 = gelu_tanh(v1); }
                    reinterpret_cast<uint32_t*>(Ch)[off >> 1] = pack1(v0, v1);
                } else {
                    if (Rsd) {
                        float2 r = *reinterpret_cast<const float2*>(Rsd + off);
                        v0 += r.x; v1 += r.y;
                    }
                    *reinterpret_cast<float2*>(Cf + off) = make_float2(v0, v1);
                }
            }
        }
    }
}

#define GEMM_SMEM_128 (4*(128+128)*SEB*2)   /* 81920 */
#define GEMM_SMEM_64  (4*( 64+128)*SEB*2)   /* 61440 */

/* ---------------- launch --------------------------------------------------- */
extern "C" void kernel_launch(void* const* d_in, const int* in_sizes, int n_in,
                              void* d_out, int out_size)
{
    const float* x     = (const float*)d_in[0];
    const float* ln1s  = (const float*)d_in[1];
    const float* ln1b  = (const float*)d_in[2];
    const float* qkvw  = (const float*)d_in[3];
    const float* qkvb  = (const float*)d_in[4];
    const float* projw = (const float*)d_in[5];
    const float* projb = (const float*)d_in[6];
    const float* ln2s  = (const float*)d_in[7];
    const float* ln2b  = (const float*)d_in[8];
    const float* fc1w  = (const float*)d_in[9];
    const float* fc1b  = (const float*)d_in[10];
    const float* fc2w  = (const float*)d_in[11];
    const float* fc2b  = (const float*)d_in[12];
    float* out = (float*)d_out;

    hf *y, *qkvh, *att, *hb, *wq, *wp, *w1, *w2;
    float *x1;
    cudaGetSymbolAddress((void**)&y,    g_y);
    cudaGetSymbolAddress((void**)&qkvh, g_qkv);
    cudaGetSymbolAddress((void**)&att,  g_att);
    cudaGetSymbolAddress((void**)&x1,   g_x1);
    cudaGetSymbolAddress((void**)&hb,   g_h);
    cudaGetSymbolAddress((void**)&wq,   g_wq);
    cudaGetSymbolAddress((void**)&wp,   g_wp);
    cudaGetSymbolAddress((void**)&w1,   g_w1);
    cudaGetSymbolAddress((void**)&w2,   g_w2);

    cudaFuncSetAttribute(flash_kernel,
        cudaFuncAttributeMaxDynamicSharedMemorySize, FA_SMEM);
    cudaFuncSetAttribute(gemm_hf<128>,
        cudaFuncAttributeMaxDynamicSharedMemorySize, GEMM_SMEM_128);
    cudaFuncSetAttribute(gemm_hf<64>,
        cudaFuncAttributeMaxDynamicSharedMemorySize, GEMM_SMEM_64);

    /* 0. all weight transposes, one launch */
    wt_all_kernel<<<6912, dim3(32,8)>>>(qkvw, projw, fc1w, fc2w, wq, wp, w1, w2);

    /* 1. LN1 -> y fp16 */
    ln_kernel<<<ROWS, 256>>>(x, ln1s, ln1b, y);

    /* 2. QKV = y @ Wq + b  (fp16 out) */
    gemm_hf<128><<<dim3(3*DIM/BN, ROWS/128), 256, GEMM_SMEM_128>>>(
        y, wq, qkvb, nullptr, nullptr, qkvh, 0,
        ROWS, 3*DIM, DIM);

    /* 3-5. flash attention -> att fp16 (4 warps, ldmatrix) */
    flash_kernel<<<dim3(SEQ / BQ, BATCH * HEADS), 128, FA_SMEM>>>(qkvh, att);

    /* 6. x1 = att @ Wp + b + x  (f32 out) */
    gemm_hf<64><<<dim3(DIM/BN, ROWS/64), 128, GEMM_SMEM_64>>>(
        att, wp, projb, x, x1, nullptr, 0,
        ROWS, DIM, DIM);

    /* 7. LN2 -> y fp16 */
    ln_kernel<<<ROWS, 256>>>(x1, ln2s, ln2b, y);

    /* 8. h = gelu(y @ W1 + b)  (fp16 out) */
    gemm_hf<128><<<dim3(HIDDEN/BN, ROWS/128), 256, GEMM_SMEM_128>>>(
        y, w1, fc1b, nullptr, nullptr, hb, 1,
        ROWS, HIDDEN, DIM);

    /* 9. out = h @ W2 + b + x1  (f32 out) */
    gemm_hf<64><<<dim3(DIM/BN, ROWS/64), 128, GEMM_SMEM_64>>>(
        hb, w2, fc2b, x1, out, nullptr, 0,
        ROWS, DIM, HIDDEN);
}

// round 14
// speedup vs baseline: 1.0788x; 1.0296x over previous
#include <cuda_runtime.h>
#include <cuda_fp16.h>
#include <cstdint>

#define DIM    768
#define SEQ    1024
#define BATCH  8
#define ROWS   (BATCH*SEQ)      /* 8192 */
#define HEADS  12
#define HD     64
#define HIDDEN 3072
#define LN_EPS 1e-6f

typedef __half hf;

/* ---------------- scratch (static device globals; no allocations) -------- */
__device__ __align__(16) hf    g_y  [ROWS * DIM];
__device__ __align__(16) hf    g_qkv[ROWS * 3 * DIM];
__device__ __align__(16) hf    g_att[ROWS * DIM];
__device__ __align__(16) float g_x1 [ROWS * DIM];
__device__ __align__(16) hf    g_h  [ROWS * HIDDEN];
__device__ __align__(16) hf g_wq[3*DIM*DIM];
__device__ __align__(16) hf g_wp[DIM*DIM];
__device__ __align__(16) hf g_w1[HIDDEN*DIM];
__device__ __align__(16) hf g_w2[DIM*HIDDEN];

/* ---------------- helpers -------------------------------------------------- */
__device__ __forceinline__ float gelu_tanh(float u)
{
    return 0.5f * u * (1.0f + tanhf(0.7978845608028654f * (u + 0.044715f * u * u * u)));
}

__device__ __forceinline__ void mma16816(
    float& c0, float& c1, float& c2, float& c3,
    uint32_t a0, uint32_t a1, uint32_t a2, uint32_t a3,
    uint32_t b0, uint32_t b1)
{
    asm volatile(
        "mma.sync.aligned.m16n8k16.row.col.f32.f16.f16.f32 "
        "{%0,%1,%2,%3},{%4,%5,%6,%7},{%8,%9},{%0,%1,%2,%3};"
        : "+f"(c0), "+f"(c1), "+f"(c2), "+f"(c3)
        : "r"(a0), "r"(a1), "r"(a2), "r"(a3), "r"(b0), "r"(b1));
}

__device__ __forceinline__ uint32_t pack1(float x0, float x1)
{
    hf h0 = __float2half_rn(x0), h1 = __float2half_rn(x1);
    return ((uint32_t)__half_as_ushort(h1) << 16) | __half_as_ushort(h0);
}

__device__ __forceinline__ void cp16(uint32_t s, const void* g)
{
    asm volatile("cp.async.cg.shared.global [%0], [%1], 16;" :: "r"(s), "l"(g));
}
__device__ __forceinline__ void ldm_x4(uint32_t* r, uint32_t addr)
{
    asm volatile("ldmatrix.sync.aligned.m8n8.x4.shared.b16 {%0,%1,%2,%3}, [%4];"
        : "=r"(r[0]), "=r"(r[1]), "=r"(r[2]), "=r"(r[3]) : "r"(addr));
}

/* ---------------- merged weight transpose ---------------------------------- */
__global__ void __launch_bounds__(256) wt_all_kernel(
    const float* __restrict__ qkvw, const float* __restrict__ projw,
    const float* __restrict__ fc1w, const float* __restrict__ fc2w,
    hf* __restrict__ wq, hf* __restrict__ wp,
    hf* __restrict__ w1, hf* __restrict__ w2)
{
    int id = blockIdx.x;
    const float* W; hf* T; int K, N, tile;
    if (id < 1728)      { W = qkvw; T = wq; K = DIM;    N = 3*DIM;  tile = id; }
    else if (id < 2304) { W = projw; T = wp; K = DIM;   N = DIM;    tile = id - 1728; }
    else if (id < 4608) { W = fc1w; T = w1; K = DIM;    N = HIDDEN; tile = id - 2304; }
    else                { W = fc2w; T = w2; K = HIDDEN; N = DIM;    tile = id - 4608; }
    int nx = N >> 5;
    int n0 = (tile % nx) << 5, k0 = (tile / nx) << 5;

    __shared__ float s[32][33];
    int tx = threadIdx.x, ty = threadIdx.y;
    #pragma unroll
    for (int j = 0; j < 4; j++)
        s[ty + j*8][tx] = W[(long)(k0 + ty + j*8) * N + n0 + tx];
    __syncthreads();
    #pragma unroll
    for (int j = 0; j < 4; j++) {
        long o = (long)(n0 + ty + j*8) * K + k0 + tx;
        T[o] = __float2half_rn(s[tx][ty + j*8]);
    }
}

/* ---------------- layernorm -> single fp16 --------------------------------- */
__global__ void __launch_bounds__(256) ln_kernel(
    const float* __restrict__ x, const float* __restrict__ sc,
    const float* __restrict__ bi, hf* __restrict__ y)
{
    long row = blockIdx.x;
    int  t   = threadIdx.x;
    const float* xr = x + row * DIM;
    float v0 = xr[t], v1 = xr[t + 256], v2 = xr[t + 512];

    __shared__ float sbuf[8];
    __shared__ float s_mu, s_r;

    float s = v0 + v1 + v2;
    #pragma unroll
    for (int o = 16; o > 0; o >>= 1) s += __shfl_xor_sync(0xffffffffu, s, o);
    if ((t & 31) == 0) sbuf[t >> 5] = s;
    __syncthreads();
    if (t < 8) {
        float r = sbuf[t];
        #pragma unroll
        for (int o = 4; o > 0; o >>= 1) r += __shfl_xor_sync(0xffu, r, o);
        if (t == 0) s_mu = r * (1.0f / DIM);
    }
    __syncthreads();
    float mu = s_mu;
    float d0 = v0 - mu, d1 = v1 - mu, d2 = v2 - mu;
    float q = d0*d0 + d1*d1 + d2*d2;
    #pragma unroll
    for (int o = 16; o > 0; o >>= 1) q += __shfl_xor_sync(0xffffffffu, q, o);
    if ((t & 31) == 0) sbuf[t >> 5] = q;
    __syncthreads();
    if (t < 8) {
        float r = sbuf[t];
        #pragma unroll
        for (int o = 4; o > 0; o >>= 1) r += __shfl_xor_sync(0xffu, r, o);
        if (t == 0) s_r = rsqrtf(r * (1.0f / DIM) + LN_EPS);
    }
    __syncthreads();
    float rs = s_r;
    long base = row * DIM;
    y[base + t      ] = __float2half_rn(d0 * rs * sc[t      ] + bi[t      ]);
    y[base + t + 256] = __float2half_rn(d1 * rs * sc[t + 256] + bi[t + 256]);
    y[base + t + 512] = __float2half_rn(d2 * rs * sc[t + 512] + bi[t + 512]);
}

/* ================= flash attention: 4 warps x 32 q-rows, ldmatrix (R13) ==== */
#define BQ  128
#define BKV 64
#define QST 72
#define SQ_ELE (BQ*QST)
#define SK_ELE (BKV*QST)
#define FA_SMEM ((SQ_ELE + 2*SK_ELE + SK_ELE) * 2)   /* 46080 B */

__global__ void __launch_bounds__(128) flash_kernel(
    const hf* __restrict__ qkv, hf* __restrict__ att)
{
    extern __shared__ hf sm[];
    hf* Vs  = sm + SQ_ELE + 2*SK_ELE;
    uint32_t* VW = reinterpret_cast<uint32_t*>(Vs);
    uint32_t sQ, sK0, sV;
    {
        uint32_t base = (uint32_t)__cvta_generic_to_shared(sm);
        sQ = base; sK0 = base + SQ_ELE*2; sV = sK0 + 2*SK_ELE*2;
    }

    int t = threadIdx.x, lane = t & 31, wid = t >> 5;
    int gid = lane >> 2, tig = lane & 3;
    int t4 = lane >> 3, li = lane & 7;
    int a_row = (t4 & 1) * 8 + li,  a_col = (t4 >> 1) * 8;
    int b_row = (t4 >> 1) * 8 + li, b_col = (t4 & 1) * 8;

    int bh = blockIdx.y, b = bh / HEADS, h = bh % HEADS;
    int q0 = blockIdx.x * BQ;

    const hf* Qp = qkv + ((long)b * SEQ + q0) * (3*DIM) + h * HD;
    const hf* Kp = qkv + (long)b * SEQ * (3*DIM) + DIM     + h * HD;
    const hf* Vp = qkv + (long)b * SEQ * (3*DIM) + 2*DIM   + h * HD;

    auto issueQ = [&]() {
        #pragma unroll
        for (int i = 0; i < 8; i++) {
            int g = t + i * 128;
            int row = g >> 3, c = g & 7;
            cp16(sQ + (row*QST + c*8)*2, Qp + (long)row*(3*DIM) + c*8);
        }
    };
    auto issueK = [&](int it) {
        uint32_t kb = sK0 + (it & 1) * (SK_ELE*2);
        #pragma unroll
        for (int i = 0; i < 4; i++) {
            int g = t + i * 128;
            int row = g >> 3, c = g & 7;
            cp16(kb + (row*QST + c*8)*2, Kp + (long)(it*BKV + row)*(3*DIM) + c*8);
        }
        asm volatile("cp.async.commit_group;");
    };

    int vrp = t & 31, vdb = (t >> 5) * 16;
    uint32_t va[8], vb[8];
    auto loadV = [&](int it) {
        const hf* p0 = Vp + (long)(it * BKV + 2*vrp) * (3*DIM) + vdb;
        const hf* p1 = p0 + 3*DIM;
        uint4 a0 = *reinterpret_cast<const uint4*>(p0);
        uint4 a1 = *reinterpret_cast<const uint4*>(p0 + 8);
        uint4 b0 = *reinterpret_cast<const uint4*>(p1);
        uint4 b1 = *reinterpret_cast<const uint4*>(p1 + 8);
        va[0]=a0.x; va[1]=a0.y; va[2]=a0.z; va[3]=a0.w;
        va[4]=a1.x; va[5]=a1.y; va[6]=a1.z; va[7]=a1.w;
        vb[0]=b0.x; vb[1]=b0.y; vb[2]=b0.z; vb[3]=b0.w;
        vb[4]=b1.x; vb[5]=b1.y; vb[6]=b1.z; vb[7]=b1.w;
    };

    issueQ();
    issueK(0);
    loadV(0);

    float acc[2][8][4];
    float oacc[2][8][4];
    float mrow[2][2], lrow[2][2];
    #pragma unroll
    for (int i = 0; i < 2; i++) {
        mrow[i][0] = mrow[i][1] = -1e30f;
        lrow[i][0] = lrow[i][1] = 0.0f;
        #pragma unroll
        for (int j = 0; j < 8; j++)
            #pragma unroll
            for (int r = 0; r < 4; r++) oacc[i][j][r] = 0.0f;
    }

    int wm = wid * 32;

    for (int it = 0; it < SEQ / BKV; it++) {
        asm volatile("cp.async.wait_group 0;");
        __syncthreads();
        uint32_t sK = sK0 + (it & 1) * (SK_ELE*2);

        #pragma unroll
        for (int i = 0; i < 2; i++)
            #pragma unroll
            for (int j = 0; j < 8; j++)
                #pragma unroll
                for (int r = 0; r < 4; r++) acc[i][j][r] = 0.0f;

        #pragma unroll
        for (int ks = 0; ks < 4; ks++) {
            uint32_t qa[2][4], kb4[4][4];
            #pragma unroll
            for (int tm = 0; tm < 2; tm++)
                ldm_x4(qa[tm], sQ + ((wm + tm*16 + a_row)*QST + ks*16 + a_col)*2);
            #pragma unroll
            for (int p = 0; p < 4; p++)
                ldm_x4(kb4[p], sK + ((p*16 + b_row)*QST + ks*16 + b_col)*2);
            #pragma unroll
            for (int tn = 0; tn < 8; tn++) {
                uint32_t* kk = kb4[tn >> 1];
                uint32_t b0 = kk[(tn & 1) * 2], b1 = kk[(tn & 1) * 2 + 1];
                #pragma unroll
                for (int tm = 0; tm < 2; tm++) {
                    float* c = acc[tm][tn];
                    mma16816(c[0],c[1],c[2],c[3],
                             qa[tm][0],qa[tm][1],qa[tm][2],qa[tm][3], b0,b1);
                }
            }
        }

        #pragma unroll
        for (int tm = 0; tm < 2; tm++) {
            float mx0 = -1e30f, mx1 = -1e30f;
            #pragma unroll
            for (int tn = 0; tn < 8; tn++) {
                float* c = acc[tm][tn];
                c[0] *= 0.125f; c[1] *= 0.125f; c[2] *= 0.125f; c[3] *= 0.125f;
                mx0 = fmaxf(mx0, fmaxf(c[0], c[1]));
                mx1 = fmaxf(mx1, fmaxf(c[2], c[3]));
            }
            #pragma unroll
            for (int o = 1; o <= 2; o <<= 1) {
                mx0 = fmaxf(mx0, __shfl_xor_sync(0xffffffffu, mx0, o));
                mx1 = fmaxf(mx1, __shfl_xor_sync(0xffffffffu, mx1, o));
            }
            float mn0 = fmaxf(mrow[tm][0], mx0);
            float mn1 = fmaxf(mrow[tm][1], mx1);
            float sc0 = __expf(mrow[tm][0] - mn0);
            float sc1 = __expf(mrow[tm][1] - mn1);
            float ls0 = 0.0f, ls1 = 0.0f;
            #pragma unroll
            for (int tn = 0; tn < 8; tn++) {
                float* c = acc[tm][tn];
                c[0] = __expf(c[0] - mn0);
                c[1] = __expf(c[1] - mn0);
                c[2] = __expf(c[2] - mn1);
                c[3] = __expf(c[3] - mn1);
                ls0 += c[0] + c[1];
                ls1 += c[2] + c[3];
            }
            #pragma unroll
            for (int o = 1; o <= 2; o <<= 1) {
                ls0 += __shfl_xor_sync(0xffffffffu, ls0, o);
                ls1 += __shfl_xor_sync(0xffffffffu, ls1, o);
            }
            lrow[tm][0] = lrow[tm][0] * sc0 + ls0;
            lrow[tm][1] = lrow[tm][1] * sc1 + ls1;
            mrow[tm][0] = mn0;
            mrow[tm][1] = mn1;
            #pragma unroll
            for (int to = 0; to < 8; to++) {
                oacc[tm][to][0] *= sc0; oacc[tm][to][1] *= sc0;
                oacc[tm][to][2] *= sc1; oacc[tm][to][3] *= sc1;
            }
        }

        #pragma unroll
        for (int k = 0; k < 8; k++) {
            VW[(vdb + 2*k    ) * (QST/2) + vrp] = __byte_perm(va[k], vb[k], 0x5410);
            VW[(vdb + 2*k + 1) * (QST/2) + vrp] = __byte_perm(va[k], vb[k], 0x7632);
        }
        if (it + 1 < SEQ / BKV) {
            issueK(it + 1);
            loadV(it + 1);
        }
        __syncthreads();

        #pragma unroll
        for (int j = 0; j < 4; j++) {
            uint32_t pH[2][4];
            #pragma unroll
            for (int tm = 0; tm < 2; tm++) {
                pH[tm][0] = pack1(acc[tm][2*j  ][0], acc[tm][2*j  ][1]);
                pH[tm][1] = pack1(acc[tm][2*j  ][2], acc[tm][2*j  ][3]);
                pH[tm][2] = pack1(acc[tm][2*j+1][0], acc[tm][2*j+1][1]);
                pH[tm][3] = pack1(acc[tm][2*j+1][2], acc[tm][2*j+1][3]);
            }
            uint32_t vb4[4][4];
            #pragma unroll
            for (int p = 0; p < 4; p++)
                ldm_x4(vb4[p], sV + ((p*16 + b_row)*QST + j*16 + b_col)*2);
            #pragma unroll
            for (int to = 0; to < 8; to++) {
                uint32_t* vv = vb4[to >> 1];
                uint32_t b0 = vv[(to & 1) * 2], b1 = vv[(to & 1) * 2 + 1];
                #pragma unroll
                for (int tm = 0; tm < 2; tm++) {
                    float* c = oacc[tm][to];
                    mma16816(c[0],c[1],c[2],c[3],
                             pH[tm][0],pH[tm][1],pH[tm][2],pH[tm][3], b0,b1);
                }
            }
        }
    }

    uint32_t* AW = reinterpret_cast<uint32_t*>(att);
    #pragma unroll
    for (int tm = 0; tm < 2; tm++) {
        float inv0 = 1.0f / lrow[tm][0];
        float inv1 = 1.0f / lrow[tm][1];
        int row = q0 + wm + tm*16 + gid;
        #pragma unroll
        for (int to = 0; to < 8; to++) {
            int col = h*HD + to*8 + tig*2;
            float* c = oacc[tm][to];
            long o0 = (((long)b*SEQ + row    ) * DIM + col) >> 1;
            long o1 = (((long)b*SEQ + row + 8) * DIM + col) >> 1;
            AW[o0] = pack1(c[0]*inv0, c[1]*inv0);
            AW[o1] = pack1(c[2]*inv1, c[3]*inv1);
        }
    }
}

/* ================= dense GEMM: fp16, BK=64, 2-stage, issue-after-sync ======
 * Half the barriers of the BK=32 version. Same K-order per accumulator ->
 * bit-identical. BMT=128: 256 thr, 2 CTAs/SM. BMT=64: 128 thr, 3 CTAs/SM.
 */
#define BN   128
#define BK2  64
#define SEB2 72

template <int BMT>
__global__ void __launch_bounds__(BMT*2, (BMT==128)?2:3) gemm_hf(
    const hf* __restrict__ Ag, const hf* __restrict__ Bg,
    const float* __restrict__ bias, const float* __restrict__ Rsd,
    float* __restrict__ Cf, hf* __restrict__ Ch, int doGelu,
    int M, int N, int K)
{
    constexpr int TSZA = BMT * SEB2;
    constexpr int TSZB = BN  * SEB2;
    extern __shared__ hf gsm[];
    uint32_t sbase = (uint32_t)__cvta_generic_to_shared(gsm);

    int m0 = blockIdx.y * BMT;
    int n0 = blockIdx.x * BN;
    int t  = threadIdx.x;
    int lane = t & 31, wid = t >> 5;
    int gid = lane >> 2, tig = lane & 3;
    int warp_m = (BMT == 128) ? ((wid >> 2) << 6) : 0;
    int warp_n = (wid & 3) << 5;

    /* loader: 8 cols of 16B per row; thread t covers row t>>3, col16 t&7 */
    int lrow = t >> 3, lcol = (t & 7) * 8;

    auto issue = [&](int st) {
        int buf = st & 1;
        long k0 = (long)st * BK2;
        uint32_t dA = sbase + (buf*TSZA)*2;
        uint32_t dB = sbase + (2*TSZA + buf*TSZB)*2;
        /* A: BMT rows x 64 cols; threads cover BMT*8 chunks in BMT*2/ (BMT*2 thr /8...) */
        #pragma unroll
        for (int i = 0; i < 4; i++) {       /* BMT*8 chunks / (BMT*2 thr) = 4 */
            int row = lrow + i * (BMT/4);
            cp16(dA + (row*SEB2 + lcol)*2, Ag + (long)(m0 + row)*K + k0 + lcol);
        }
        #pragma unroll
        for (int i = 0; i < (BMT==128 ? 4 : 8); i++) {  /* B: 128*8 chunks */
            int row = lrow + i * (BMT==128 ? 32 : 16);
            cp16(dB + (row*SEB2 + lcol)*2, Bg + (long)(n0 + row)*K + k0 + lcol);
        }
        asm volatile("cp.async.commit_group;");
    };

    float acc[4][4][4];
    #pragma unroll
    for (int i = 0; i < 4; i++)
        #pragma unroll
        for (int j = 0; j < 4; j++)
            #pragma unroll
            for (int r = 0; r < 4; r++) acc[i][j][r] = 0.0f;

    int t4 = lane >> 3, li = lane & 7;
    int a_row = (t4 & 1) * 8 + li,  a_col = (t4 >> 1) * 8;
    int b_row = (t4 >> 1) * 8 + li, b_col = (t4 & 1) * 8;

    int kt = K / BK2;
    issue(0);

    for (int kk = 0; kk < kt; kk++) {
        asm volatile("cp.async.wait_group 0;");
        __syncthreads();
        if (kk + 1 < kt) issue(kk + 1);   /* after sync: prev buffer fully consumed */

        int buf = kk & 1;
        uint32_t sA = sbase + (buf*TSZA)*2;
        uint32_t sB = sbase + (2*TSZA + buf*TSZB)*2;

        #pragma unroll
        for (int ks = 0; ks < 4; ks++) {
            int kc = ks * 16;
            uint32_t a[4][4], bb2[2][4];
            #pragma unroll
            for (int tm = 0; tm < 4; tm++)
                ldm_x4(a[tm], sA + ((warp_m + tm*16 + a_row)*SEB2 + kc + a_col)*2);
            #pragma unroll
            for (int p = 0; p < 2; p++)
                ldm_x4(bb2[p], sB + ((warp_n + p*16 + b_row)*SEB2 + kc + b_col)*2);

            #pragma unroll
            for (int tm = 0; tm < 4; tm++)
                #pragma unroll
                for (int tn = 0; tn < 4; tn++) {
                    float* c = acc[tm][tn];
                    uint32_t* bb = bb2[tn >> 1];
                    mma16816(c[0],c[1],c[2],c[3],
                             a[tm][0],a[tm][1],a[tm][2],a[tm][3],
                             bb[(tn&1)*2], bb[(tn&1)*2+1]);
                }
        }
        __syncthreads();   /* buffer consumed before next iteration's overwrite-issue */
    }

    /* epilogue */
    #pragma unroll
    for (int tn = 0; tn < 4; tn++) {
        int col = n0 + warp_n + tn * 8 + tig * 2;
        float b0 = bias ? bias[col]     : 0.0f;
        float b1 = bias ? bias[col + 1] : 0.0f;
        #pragma unroll
        for (int tm = 0; tm < 4; tm++) {
            int row0 = m0 + warp_m + tm * 16 + gid;
            float* c = acc[tm][tn];
            #pragma unroll
            for (int half = 0; half < 2; half++) {
                int row = row0 + half * 8;
                float v0 = c[half*2 + 0] + b0;
                float v1 = c[half*2 + 1] + b1;
                long off = (long)row * N + col;
                if (Ch) {
                    if (doGelu) { v0 = gelu_tanh(v0); v1 = gelu_tanh(v1); }
                    reinterpret_cast<uint32_t*>(Ch)[off >> 1] = pack1(v0, v1);
                } else {
                    if (Rsd) {
                        float2 r = *reinterpret_cast<const float2*>(Rsd + off);
                        v0 += r.x; v1 += r.y;
                    }
                    *reinterpret_cast<float2*>(Cf + off) = make_float2(v0, v1);
                }
            }
        }
    }
}

#define GEMM_SMEM_128 (2*(128+128)*SEB2*2)   /* 73728 */
#define GEMM_SMEM_64  (2*( 64+128)*SEB2*2)   /* 55296 */

/* ---------------- launch --------------------------------------------------- */
extern "C" void kernel_launch(void* const* d_in, const int* in_sizes, int n_in,
                              void* d_out, int out_size)
{
    const float* x     = (const float*)d_in[0];
    const float* ln1s  = (const float*)d_in[1];
    const float* ln1b  = (const float*)d_in[2];
    const float* qkvw  = (const float*)d_in[3];
    const float* qkvb  = (const float*)d_in[4];
    const float* projw = (const float*)d_in[5];
    const float* projb = (const float*)d_in[6];
    const float* ln2s  = (const float*)d_in[7];
    const float* ln2b  = (const float*)d_in[8];
    const float* fc1w  = (const float*)d_in[9];
    const float* fc1b  = (const float*)d_in[10];
    const float* fc2w  = (const float*)d_in[11];
    const float* fc2b  = (const float*)d_in[12];
    float* out = (float*)d_out;

    hf *y, *qkvh, *att, *hb, *wq, *wp, *w1, *w2;
    float *x1;
    cudaGetSymbolAddress((void**)&y,    g_y);
    cudaGetSymbolAddress((void**)&qkvh, g_qkv);
    cudaGetSymbolAddress((void**)&att,  g_att);
    cudaGetSymbolAddress((void**)&x1,   g_x1);
    cudaGetSymbolAddress((void**)&hb,   g_h);
    cudaGetSymbolAddress((void**)&wq,   g_wq);
    cudaGetSymbolAddress((void**)&wp,   g_wp);
    cudaGetSymbolAddress((void**)&w1,   g_w1);
    cudaGetSymbolAddress((void**)&w2,   g_w2);

    cudaFuncSetAttribute(flash_kernel,
        cudaFuncAttributeMaxDynamicSharedMemorySize, FA_SMEM);
    cudaFuncSetAttribute(gemm_hf<128>,
        cudaFuncAttributeMaxDynamicSharedMemorySize, GEMM_SMEM_128);
    cudaFuncSetAttribute(gemm_hf<64>,
        cudaFuncAttributeMaxDynamicSharedMemorySize, GEMM_SMEM_64);

    /* 0. all weight transposes, one launch */
    wt_all_kernel<<<6912, dim3(32,8)>>>(qkvw, projw, fc1w, fc2w, wq, wp, w1, w2);

    /* 1. LN1 -> y fp16 */
    ln_kernel<<<ROWS, 256>>>(x, ln1s, ln1b, y);

    /* 2. QKV = y @ Wq + b  (fp16 out) */
    gemm_hf<128><<<dim3(3*DIM/BN, ROWS/128), 256, GEMM_SMEM_128>>>(
        y, wq, qkvb, nullptr, nullptr, qkvh, 0,
        ROWS, 3*DIM, DIM);

    /* 3-5. flash attention -> att fp16 */
    flash_kernel<<<dim3(SEQ / BQ, BATCH * HEADS), 128, FA_SMEM>>>(qkvh, att);

    /* 6. x1 = att @ Wp + b + x  (f32 out) */
    gemm_hf<64><<<dim3(DIM/BN, ROWS/64), 128, GEMM_SMEM_64>>>(
        att, wp, projb, x, x1, nullptr, 0,
        ROWS, DIM, DIM);

    /* 7. LN2 -> y fp16 */
    ln_kernel<<<ROWS, 256>>>(x1, ln2s, ln2b, y);

    /* 8. h = gelu(y @ W1 + b)  (fp16 out) */
    gemm_hf<128><<<dim3(HIDDEN/BN, ROWS/128), 256, GEMM_SMEM_128>>>(
        y, w1, fc1b, nullptr, nullptr, hb, 1,
        ROWS, HIDDEN, DIM);

    /* 9. out = h @ W2 + b + x1  (f32 out) */
    gemm_hf<64><<<dim3(DIM/BN, ROWS/64), 128, GEMM_SMEM_64>>>(
        hb, w2, fc2b, x1, out, nullptr, 0,
        ROWS, DIM, HIDDEN);
}

// round 15
// speedup vs baseline: 1.1018x; 1.0214x over previous
#include <cuda_runtime.h>
#include <cuda_fp16.h>
#include <cstdint>

#define DIM    768
#define SEQ    1024
#define BATCH  8
#define ROWS   (BATCH*SEQ)      /* 8192 */
#define HEADS  12
#define HD     64
#define HIDDEN 3072
#define LN_EPS 1e-6f
#define S2LOG  0.1803368801111244f   /* 0.125 * log2(e) */

typedef __half hf;

/* ---------------- scratch (static device globals; no allocations) -------- */
__device__ __align__(16) hf    g_y  [ROWS * DIM];
__device__ __align__(16) hf    g_qkv[ROWS * 3 * DIM];
__device__ __align__(16) hf    g_att[ROWS * DIM];
__device__ __align__(16) float g_x1 [ROWS * DIM];
__device__ __align__(16) hf    g_h  [ROWS * HIDDEN];
__device__ __align__(16) hf g_wq[3*DIM*DIM];
__device__ __align__(16) hf g_wp[DIM*DIM];
__device__ __align__(16) hf g_w1[HIDDEN*DIM];
__device__ __align__(16) hf g_w2[DIM*HIDDEN];

/* ---------------- helpers -------------------------------------------------- */
__device__ __forceinline__ float gelu_tanh(float u)
{
    return 0.5f * u * (1.0f + tanhf(0.7978845608028654f * (u + 0.044715f * u * u * u)));
}

__device__ __forceinline__ void mma16816(
    float& c0, float& c1, float& c2, float& c3,
    uint32_t a0, uint32_t a1, uint32_t a2, uint32_t a3,
    uint32_t b0, uint32_t b1)
{
    asm volatile(
        "mma.sync.aligned.m16n8k16.row.col.f32.f16.f16.f32 "
        "{%0,%1,%2,%3},{%4,%5,%6,%7},{%8,%9},{%0,%1,%2,%3};"
        : "+f"(c0), "+f"(c1), "+f"(c2), "+f"(c3)
        : "r"(a0), "r"(a1), "r"(a2), "r"(a3), "r"(b0), "r"(b1));
}

__device__ __forceinline__ uint32_t pack1(float x0, float x1)
{
    hf h0 = __float2half_rn(x0), h1 = __float2half_rn(x1);
    return ((uint32_t)__half_as_ushort(h1) << 16) | __half_as_ushort(h0);
}

__device__ __forceinline__ void cp16(uint32_t s, const void* g)
{
    asm volatile("cp.async.cg.shared.global [%0], [%1], 16;" :: "r"(s), "l"(g));
}
__device__ __forceinline__ void ldm_x4(uint32_t* r, uint32_t addr)
{
    asm volatile("ldmatrix.sync.aligned.m8n8.x4.shared.b16 {%0,%1,%2,%3}, [%4];"
        : "=r"(r[0]), "=r"(r[1]), "=r"(r[2]), "=r"(r[3]) : "r"(addr));
}

/* ---------------- merged weight transpose ---------------------------------- */
__global__ void __launch_bounds__(256) wt_all_kernel(
    const float* __restrict__ qkvw, const float* __restrict__ projw,
    const float* __restrict__ fc1w, const float* __restrict__ fc2w,
    hf* __restrict__ wq, hf* __restrict__ wp,
    hf* __restrict__ w1, hf* __restrict__ w2)
{
    int id = blockIdx.x;
    const float* W; hf* T; int K, N, tile;
    if (id < 1728)      { W = qkvw; T = wq; K = DIM;    N = 3*DIM;  tile = id; }
    else if (id < 2304) { W = projw; T = wp; K = DIM;   N = DIM;    tile = id - 1728; }
    else if (id < 4608) { W = fc1w; T = w1; K = DIM;    N = HIDDEN; tile = id - 2304; }
    else                { W = fc2w; T = w2; K = HIDDEN; N = DIM;    tile = id - 4608; }
    int nx = N >> 5;
    int n0 = (tile % nx) << 5, k0 = (tile / nx) << 5;

    __shared__ float s[32][33];
    int tx = threadIdx.x, ty = threadIdx.y;
    #pragma unroll
    for (int j = 0; j < 4; j++)
        s[ty + j*8][tx] = W[(long)(k0 + ty + j*8) * N + n0 + tx];
    __syncthreads();
    #pragma unroll
    for (int j = 0; j < 4; j++) {
        long o = (long)(n0 + ty + j*8) * K + k0 + tx;
        T[o] = __float2half_rn(s[tx][ty + j*8]);
    }
}

/* ---------------- layernorm -> single fp16 --------------------------------- */
__global__ void __launch_bounds__(256) ln_kernel(
    const float* __restrict__ x, const float* __restrict__ sc,
    const float* __restrict__ bi, hf* __restrict__ y)
{
    long row = blockIdx.x;
    int  t   = threadIdx.x;
    const float* xr = x + row * DIM;
    float v0 = xr[t], v1 = xr[t + 256], v2 = xr[t + 512];

    __shared__ float sbuf[8];
    __shared__ float s_mu, s_r;

    float s = v0 + v1 + v2;
    #pragma unroll
    for (int o = 16; o > 0; o >>= 1) s += __shfl_xor_sync(0xffffffffu, s, o);
    if ((t & 31) == 0) sbuf[t >> 5] = s;
    __syncthreads();
    if (t < 8) {
        float r = sbuf[t];
        #pragma unroll
        for (int o = 4; o > 0; o >>= 1) r += __shfl_xor_sync(0xffu, r, o);
        if (t == 0) s_mu = r * (1.0f / DIM);
    }
    __syncthreads();
    float mu = s_mu;
    float d0 = v0 - mu, d1 = v1 - mu, d2 = v2 - mu;
    float q = d0*d0 + d1*d1 + d2*d2;
    #pragma unroll
    for (int o = 16; o > 0; o >>= 1) q += __shfl_xor_sync(0xffffffffu, q, o);
    if ((t & 31) == 0) sbuf[t >> 5] = q;
    __syncthreads();
    if (t < 8) {
        float r = sbuf[t];
        #pragma unroll
        for (int o = 4; o > 0; o >>= 1) r += __shfl_xor_sync(0xffu, r, o);
        if (t == 0) s_r = rsqrtf(r * (1.0f / DIM) + LN_EPS);
    }
    __syncthreads();
    float rs = s_r;
    long base = row * DIM;
    y[base + t      ] = __float2half_rn(d0 * rs * sc[t      ] + bi[t      ]);
    y[base + t + 256] = __float2half_rn(d1 * rs * sc[t + 256] + bi[t + 256]);
    y[base + t + 512] = __float2half_rn(d2 * rs * sc[t + 512] + bi[t + 512]);
}

/* ================= flash attention: 4w x 32 q-rows, Q hoisted, exp2 ======== */
#define BQ  128
#define BKV 64
#define QST 72
#define SQ_ELE (BQ*QST)
#define SK_ELE (BKV*QST)
#define FA_SMEM ((SQ_ELE + 2*SK_ELE + SK_ELE) * 2)   /* 46080 B */

__global__ void __launch_bounds__(128, 2) flash_kernel(
    const hf* __restrict__ qkv, hf* __restrict__ att)
{
    extern __shared__ hf sm[];
    hf* Vs  = sm + SQ_ELE + 2*SK_ELE;
    uint32_t* VW = reinterpret_cast<uint32_t*>(Vs);
    uint32_t sQ, sK0, sV;
    {
        uint32_t base = (uint32_t)__cvta_generic_to_shared(sm);
        sQ = base; sK0 = base + SQ_ELE*2; sV = sK0 + 2*SK_ELE*2;
    }

    int t = threadIdx.x, lane = t & 31, wid = t >> 5;
    int gid = lane >> 2, tig = lane & 3;
    int t4 = lane >> 3, li = lane & 7;
    int a_row = (t4 & 1) * 8 + li,  a_col = (t4 >> 1) * 8;
    int b_row = (t4 >> 1) * 8 + li, b_col = (t4 & 1) * 8;

    int bh = blockIdx.y, b = bh / HEADS, h = bh % HEADS;
    int q0 = blockIdx.x * BQ;

    const hf* Qp = qkv + ((long)b * SEQ + q0) * (3*DIM) + h * HD;
    const hf* Kp = qkv + (long)b * SEQ * (3*DIM) + DIM     + h * HD;
    const hf* Vp = qkv + (long)b * SEQ * (3*DIM) + 2*DIM   + h * HD;

    auto issueQ = [&]() {
        #pragma unroll
        for (int i = 0; i < 8; i++) {
            int g = t + i * 128;
            int row = g >> 3, c = g & 7;
            cp16(sQ + (row*QST + c*8)*2, Qp + (long)row*(3*DIM) + c*8);
        }
    };
    auto issueK = [&](int it) {
        uint32_t kb = sK0 + (it & 1) * (SK_ELE*2);
        #pragma unroll
        for (int i = 0; i < 4; i++) {
            int g = t + i * 128;
            int row = g >> 3, c = g & 7;
            cp16(kb + (row*QST + c*8)*2, Kp + (long)(it*BKV + row)*(3*DIM) + c*8);
        }
        asm volatile("cp.async.commit_group;");
    };

    int vrp = t & 31, vdb = (t >> 5) * 16;
    uint32_t va[8], vb[8];
    auto loadV = [&](int it) {
        const hf* p0 = Vp + (long)(it * BKV + 2*vrp) * (3*DIM) + vdb;
        const hf* p1 = p0 + 3*DIM;
        uint4 a0 = *reinterpret_cast<const uint4*>(p0);
        uint4 a1 = *reinterpret_cast<const uint4*>(p0 + 8);
        uint4 b0 = *reinterpret_cast<const uint4*>(p1);
        uint4 b1 = *reinterpret_cast<const uint4*>(p1 + 8);
        va[0]=a0.x; va[1]=a0.y; va[2]=a0.z; va[3]=a0.w;
        va[4]=a1.x; va[5]=a1.y; va[6]=a1.z; va[7]=a1.w;
        vb[0]=b0.x; vb[1]=b0.y; vb[2]=b0.z; vb[3]=b0.w;
        vb[4]=b1.x; vb[5]=b1.y; vb[6]=b1.z; vb[7]=b1.w;
    };

    issueQ();
    issueK(0);
    loadV(0);

    /* wait for Q (+K0) and hoist all Q fragments into registers */
    asm volatile("cp.async.wait_group 0;");
    __syncthreads();
    int wm = wid * 32;
    uint32_t qf[4][2][4];
    #pragma unroll
    for (int ks = 0; ks < 4; ks++)
        #pragma unroll
        for (int tm = 0; tm < 2; tm++)
            ldm_x4(qf[ks][tm], sQ + ((wm + tm*16 + a_row)*QST + ks*16 + a_col)*2);

    float acc[2][8][4];
    float oacc[2][8][4];
    float mrow[2][2], lrow[2][2];
    #pragma unroll
    for (int i = 0; i < 2; i++) {
        mrow[i][0] = mrow[i][1] = -1e30f;
        lrow[i][0] = lrow[i][1] = 0.0f;
        #pragma unroll
        for (int j = 0; j < 8; j++)
            #pragma unroll
            for (int r = 0; r < 4; r++) oacc[i][j][r] = 0.0f;
    }

    for (int it = 0; it < SEQ / BKV; it++) {
        asm volatile("cp.async.wait_group 0;");
        __syncthreads();
        uint32_t sK = sK0 + (it & 1) * (SK_ELE*2);

        #pragma unroll
        for (int i = 0; i < 2; i++)
            #pragma unroll
            for (int j = 0; j < 8; j++)
                #pragma unroll
                for (int r = 0; r < 4; r++) acc[i][j][r] = 0.0f;

        /* S = Q @ K^T  (Q from registers, K via ldmatrix) */
        #pragma unroll
        for (int ks = 0; ks < 4; ks++) {
            uint32_t kb4[4][4];
            #pragma unroll
            for (int p = 0; p < 4; p++)
                ldm_x4(kb4[p], sK + ((p*16 + b_row)*QST + ks*16 + b_col)*2);
            #pragma unroll
            for (int tn = 0; tn < 8; tn++) {
                uint32_t* kk = kb4[tn >> 1];
                uint32_t b0 = kk[(tn & 1) * 2], b1 = kk[(tn & 1) * 2 + 1];
                #pragma unroll
                for (int tm = 0; tm < 2; tm++) {
                    float* c = acc[tm][tn];
                    mma16816(c[0],c[1],c[2],c[3],
                             qf[ks][tm][0],qf[ks][tm][1],qf[ks][tm][2],qf[ks][tm][3],
                             b0,b1);
                }
            }
        }

        /* online softmax (raw domain max; exp2-folded scale) */
        #pragma unroll
        for (int tm = 0; tm < 2; tm++) {
            float mx0 = -1e30f, mx1 = -1e30f;
            #pragma unroll
            for (int tn = 0; tn < 8; tn++) {
                float* c = acc[tm][tn];
                mx0 = fmaxf(mx0, fmaxf(c[0], c[1]));
                mx1 = fmaxf(mx1, fmaxf(c[2], c[3]));
            }
            #pragma unroll
            for (int o = 1; o <= 2; o <<= 1) {
                mx0 = fmaxf(mx0, __shfl_xor_sync(0xffffffffu, mx0, o));
                mx1 = fmaxf(mx1, __shfl_xor_sync(0xffffffffu, mx1, o));
            }
            float mn0 = fmaxf(mrow[tm][0], mx0);
            float mn1 = fmaxf(mrow[tm][1], mx1);
            float sc0 = exp2f((mrow[tm][0] - mn0) * S2LOG);
            float sc1 = exp2f((mrow[tm][1] - mn1) * S2LOG);
            float mb0 = mn0 * S2LOG;
            float mb1 = mn1 * S2LOG;
            float ls0 = 0.0f, ls1 = 0.0f;
            #pragma unroll
            for (int tn = 0; tn < 8; tn++) {
                float* c = acc[tm][tn];
                c[0] = exp2f(fmaf(c[0], S2LOG, -mb0));
                c[1] = exp2f(fmaf(c[1], S2LOG, -mb0));
                c[2] = exp2f(fmaf(c[2], S2LOG, -mb1));
                c[3] = exp2f(fmaf(c[3], S2LOG, -mb1));
                ls0 += c[0] + c[1];
                ls1 += c[2] + c[3];
            }
            #pragma unroll
            for (int o = 1; o <= 2; o <<= 1) {
                ls0 += __shfl_xor_sync(0xffffffffu, ls0, o);
                ls1 += __shfl_xor_sync(0xffffffffu, ls1, o);
            }
            lrow[tm][0] = lrow[tm][0] * sc0 + ls0;
            lrow[tm][1] = lrow[tm][1] * sc1 + ls1;
            mrow[tm][0] = mn0;
            mrow[tm][1] = mn1;
            #pragma unroll
            for (int to = 0; to < 8; to++) {
                oacc[tm][to][0] *= sc0; oacc[tm][to][1] *= sc0;
                oacc[tm][to][2] *= sc1; oacc[tm][to][3] *= sc1;
            }
        }

        /* store V tile transposed (pair-pack via prmt) */
        #pragma unroll
        for (int k = 0; k < 8; k++) {
            VW[(vdb + 2*k    ) * (QST/2) + vrp] = __byte_perm(va[k], vb[k], 0x5410);
            VW[(vdb + 2*k + 1) * (QST/2) + vrp] = __byte_perm(va[k], vb[k], 0x7632);
        }
        if (it + 1 < SEQ / BKV) {
            issueK(it + 1);
            loadV(it + 1);
        }
        __syncthreads();

        /* O += P @ V */
        #pragma unroll
        for (int j = 0; j < 4; j++) {
            uint32_t pH[2][4];
            #pragma unroll
            for (int tm = 0; tm < 2; tm++) {
                pH[tm][0] = pack1(acc[tm][2*j  ][0], acc[tm][2*j  ][1]);
                pH[tm][1] = pack1(acc[tm][2*j  ][2], acc[tm][2*j  ][3]);
                pH[tm][2] = pack1(acc[tm][2*j+1][0], acc[tm][2*j+1][1]);
                pH[tm][3] = pack1(acc[tm][2*j+1][2], acc[tm][2*j+1][3]);
            }
            uint32_t vb4[4][4];
            #pragma unroll
            for (int p = 0; p < 4; p++)
                ldm_x4(vb4[p], sV + ((p*16 + b_row)*QST + j*16 + b_col)*2);
            #pragma unroll
            for (int to = 0; to < 8; to++) {
                uint32_t* vv = vb4[to >> 1];
                uint32_t b0 = vv[(to & 1) * 2], b1 = vv[(to & 1) * 2 + 1];
                #pragma unroll
                for (int tm = 0; tm < 2; tm++) {
                    float* c = oacc[tm][to];
                    mma16816(c[0],c[1],c[2],c[3],
                             pH[tm][0],pH[tm][1],pH[tm][2],pH[tm][3], b0,b1);
                }
            }
        }
    }

    /* epilogue: O / l -> att */
    uint32_t* AW = reinterpret_cast<uint32_t*>(att);
    #pragma unroll
    for (int tm = 0; tm < 2; tm++) {
        float inv0 = 1.0f / lrow[tm][0];
        float inv1 = 1.0f / lrow[tm][1];
        int row = q0 + wm + tm*16 + gid;
        #pragma unroll
        for (int to = 0; to < 8; to++) {
            int col = h*HD + to*8 + tig*2;
            float* c = oacc[tm][to];
            long o0 = (((long)b*SEQ + row    ) * DIM + col) >> 1;
            long o1 = (((long)b*SEQ + row + 8) * DIM + col) >> 1;
            AW[o0] = pack1(c[0]*inv0, c[1]*inv0);
            AW[o1] = pack1(c[2]*inv1, c[3]*inv1);
        }
    }
}

/* ================= dense GEMM: fp16, BK=64, 2-stage (R14, unchanged) ======= */
#define BN   128
#define BK2  64
#define SEB2 72

template <int BMT>
__global__ void __launch_bounds__(BMT*2, (BMT==128)?2:3) gemm_hf(
    const hf* __restrict__ Ag, const hf* __restrict__ Bg,
    const float* __restrict__ bias, const float* __restrict__ Rsd,
    float* __restrict__ Cf, hf* __restrict__ Ch, int doGelu,
    int M, int N, int K)
{
    constexpr int TSZA = BMT * SEB2;
    constexpr int TSZB = BN  * SEB2;
    extern __shared__ hf gsm[];
    uint32_t sbase = (uint32_t)__cvta_generic_to_shared(gsm);

    int m0 = blockIdx.y * BMT;
    int n0 = blockIdx.x * BN;
    int t  = threadIdx.x;
    int lane = t & 31, wid = t >> 5;
    int gid = lane >> 2, tig = lane & 3;
    int warp_m = (BMT == 128) ? ((wid >> 2) << 6) : 0;
    int warp_n = (wid & 3) << 5;

    int lrow = t >> 3, lcol = (t & 7) * 8;

    auto issue = [&](int st) {
        int buf = st & 1;
        long k0 = (long)st * BK2;
        uint32_t dA = sbase + (buf*TSZA)*2;
        uint32_t dB = sbase + (2*TSZA + buf*TSZB)*2;
        #pragma unroll
        for (int i = 0; i < 4; i++) {
            int row = lrow + i * (BMT/4);
            cp16(dA + (row*SEB2 + lcol)*2, Ag + (long)(m0 + row)*K + k0 + lcol);
        }
        #pragma unroll
        for (int i = 0; i < (BMT==128 ? 4 : 8); i++) {
            int row = lrow + i * (BMT==128 ? 32 : 16);
            cp16(dB + (row*SEB2 + lcol)*2, Bg + (long)(n0 + row)*K + k0 + lcol);
        }
        asm volatile("cp.async.commit_group;");
    };

    float acc[4][4][4];
    #pragma unroll
    for (int i = 0; i < 4; i++)
        #pragma unroll
        for (int j = 0; j < 4; j++)
            #pragma unroll
            for (int r = 0; r < 4; r++) acc[i][j][r] = 0.0f;

    int t4 = lane >> 3, li = lane & 7;
    int a_row = (t4 & 1) * 8 + li,  a_col = (t4 >> 1) * 8;
    int b_row = (t4 >> 1) * 8 + li, b_col = (t4 & 1) * 8;

    int kt = K / BK2;
    issue(0);

    for (int kk = 0; kk < kt; kk++) {
        asm volatile("cp.async.wait_group 0;");
        __syncthreads();
        if (kk + 1 < kt) issue(kk + 1);

        int buf = kk & 1;
        uint32_t sA = sbase + (buf*TSZA)*2;
        uint32_t sB = sbase + (2*TSZA + buf*TSZB)*2;

        #pragma unroll
        for (int ks = 0; ks < 4; ks++) {
            int kc = ks * 16;
            uint32_t a[4][4], bb2[2][4];
            #pragma unroll
            for (int tm = 0; tm < 4; tm++)
                ldm_x4(a[tm], sA + ((warp_m + tm*16 + a_row)*SEB2 + kc + a_col)*2);
            #pragma unroll
            for (int p = 0; p < 2; p++)
                ldm_x4(bb2[p], sB + ((warp_n + p*16 + b_row)*SEB2 + kc + b_col)*2);

            #pragma unroll
            for (int tm = 0; tm < 4; tm++)
                #pragma unroll
                for (int tn = 0; tn < 4; tn++) {
                    float* c = acc[tm][tn];
                    uint32_t* bb = bb2[tn >> 1];
                    mma16816(c[0],c[1],c[2],c[3],
                             a[tm][0],a[tm][1],a[tm][2],a[tm][3],
                             bb[(tn&1)*2], bb[(tn&1)*2+1]);
                }
        }
        __syncthreads();
    }

    #pragma unroll
    for (int tn = 0; tn < 4; tn++) {
        int col = n0 + warp_n + tn * 8 + tig * 2;
        float b0 = bias ? bias[col]     : 0.0f;
        float b1 = bias ? bias[col + 1] : 0.0f;
        #pragma unroll
        for (int tm = 0; tm < 4; tm++) {
            int row0 = m0 + warp_m + tm * 16 + gid;
            float* c = acc[tm][tn];
            #pragma unroll
            for (int half = 0; half < 2; half++) {
                int row = row0 + half * 8;
                float v0 = c[half*2 + 0] + b0;
                float v1 = c[half*2 + 1] + b1;
                long off = (long)row * N + col;
                if (Ch) {
                    if (doGelu) { v0 = gelu_tanh(v0); v1 = gelu_tanh(v1); }
                    reinterpret_cast<uint32_t*>(Ch)[off >> 1] = pack1(v0, v1);
                } else {
                    if (Rsd) {
                        float2 r = *reinterpret_cast<const float2*>(Rsd + off);
                        v0 += r.x; v1 += r.y;
                    }
                    *reinterpret_cast<float2*>(Cf + off) = make_float2(v0, v1);
                }
            }
        }
    }
}

#define GEMM_SMEM_128 (2*(128+128)*SEB2*2)   /* 73728 */
#define GEMM_SMEM_64  (2*( 64+128)*SEB2*2)   /* 55296 */

/* ---------------- launch --------------------------------------------------- */
extern "C" void kernel_launch(void* const* d_in, const int* in_sizes, int n_in,
                              void* d_out, int out_size)
{
    const float* x     = (const float*)d_in[0];
    const float* ln1s  = (const float*)d_in[1];
    const float* ln1b  = (const float*)d_in[2];
    const float* qkvw  = (const float*)d_in[3];
    const float* qkvb  = (const float*)d_in[4];
    const float* projw = (const float*)d_in[5];
    const float* projb = (const float*)d_in[6];
    const float* ln2s  = (const float*)d_in[7];
    const float* ln2b  = (const float*)d_in[8];
    const float* fc1w  = (const float*)d_in[9];
    const float* fc1b  = (const float*)d_in[10];
    const float* fc2w  = (const float*)d_in[11];
    const float* fc2b  = (const float*)d_in[12];
    float* out = (float*)d_out;

    hf *y, *qkvh, *att, *hb, *wq, *wp, *w1, *w2;
    float *x1;
    cudaGetSymbolAddress((void**)&y,    g_y);
    cudaGetSymbolAddress((void**)&qkvh, g_qkv);
    cudaGetSymbolAddress((void**)&att,  g_att);
    cudaGetSymbolAddress((void**)&x1,   g_x1);
    cudaGetSymbolAddress((void**)&hb,   g_h);
    cudaGetSymbolAddress((void**)&wq,   g_wq);
    cudaGetSymbolAddress((void**)&wp,   g_wp);
    cudaGetSymbolAddress((void**)&w1,   g_w1);
    cudaGetSymbolAddress((void**)&w2,   g_w2);

    cudaFuncSetAttribute(flash_kernel,
        cudaFuncAttributeMaxDynamicSharedMemorySize, FA_SMEM);
    cudaFuncSetAttribute(gemm_hf<128>,
        cudaFuncAttributeMaxDynamicSharedMemorySize, GEMM_SMEM_128);
    cudaFuncSetAttribute(gemm_hf<64>,
        cudaFuncAttributeMaxDynamicSharedMemorySize, GEMM_SMEM_64);

    /* 0. all weight transposes, one launch */
    wt_all_kernel<<<6912, dim3(32,8)>>>(qkvw, projw, fc1w, fc2w, wq, wp, w1, w2);

    /* 1. LN1 -> y fp16 */
    ln_kernel<<<ROWS, 256>>>(x, ln1s, ln1b, y);

    /* 2. QKV = y @ Wq + b  (fp16 out) */
    gemm_hf<128><<<dim3(3*DIM/BN, ROWS/128), 256, GEMM_SMEM_128>>>(
        y, wq, qkvb, nullptr, nullptr, qkvh, 0,
        ROWS, 3*DIM, DIM);

    /* 3-5. flash attention -> att fp16 */
    flash_kernel<<<dim3(SEQ / BQ, BATCH * HEADS), 128, FA_SMEM>>>(qkvh, att);

    /* 6. x1 = att @ Wp + b + x  (f32 out) */
    gemm_hf<64><<<dim3(DIM/BN, ROWS/64), 128, GEMM_SMEM_64>>>(
        att, wp, projb, x, x1, nullptr, 0,
        ROWS, DIM, DIM);

    /* 7. LN2 -> y fp16 */
    ln_kernel<<<ROWS, 256>>>(x1, ln2s, ln2b, y);

    /* 8. h = gelu(y @ W1 + b)  (fp16 out) */
    gemm_hf<128><<<dim3(HIDDEN/BN, ROWS/128), 256, GEMM_SMEM_128>>>(
        y, w1, fc1b, nullptr, nullptr, hb, 1,
        ROWS, HIDDEN, DIM);

    /* 9. out = h @ W2 + b + x1  (f32 out) */
    gemm_hf<64><<<dim3(DIM/BN, ROWS/64), 128, GEMM_SMEM_64>>>(
        hb, w2, fc2b, x1, out, nullptr, 0,
        ROWS, DIM, HIDDEN);
}

// round 16
// speedup vs baseline: 1.1149x; 1.0119x over previous
#include <cuda_runtime.h>
#include <cuda_fp16.h>
#include <cstdint>

#define DIM    768
#define SEQ    1024
#define BATCH  8
#define ROWS   (BATCH*SEQ)      /* 8192 */
#define HEADS  12
#define HD     64
#define HIDDEN 3072
#define LN_EPS 1e-6f
#define S2LOG  0.1803368801111244f   /* 0.125 * log2(e) */

typedef __half hf;

/* ---------------- scratch (static device globals; no allocations) -------- */
__device__ __align__(16) hf    g_y  [ROWS * DIM];
__device__ __align__(16) hf    g_qkv[ROWS * 3 * DIM];
__device__ __align__(16) hf    g_att[ROWS * DIM];
__device__ __align__(16) float g_x1 [ROWS * DIM];
__device__ __align__(16) hf    g_h  [ROWS * HIDDEN];
__device__ __align__(16) hf g_wq[3*DIM*DIM];
__device__ __align__(16) hf g_wp[DIM*DIM];
__device__ __align__(16) hf g_w1[HIDDEN*DIM];
__device__ __align__(16) hf g_w2[DIM*HIDDEN];

/* ---------------- helpers -------------------------------------------------- */
__device__ __forceinline__ float gelu_fast(float u)
{
    /* 0.5u(1+tanh(w)) == u - u/(1+exp2(2*log2e*w)) */
    float w = 0.7978845608028654f * (u + 0.044715f * u * u * u);
    return u - __fdividef(u, 1.0f + exp2f(2.8853900817779268f * w));
}

__device__ __forceinline__ void mma16816(
    float& c0, float& c1, float& c2, float& c3,
    uint32_t a0, uint32_t a1, uint32_t a2, uint32_t a3,
    uint32_t b0, uint32_t b1)
{
    asm volatile(
        "mma.sync.aligned.m16n8k16.row.col.f32.f16.f16.f32 "
        "{%0,%1,%2,%3},{%4,%5,%6,%7},{%8,%9},{%0,%1,%2,%3};"
        : "+f"(c0), "+f"(c1), "+f"(c2), "+f"(c3)
        : "r"(a0), "r"(a1), "r"(a2), "r"(a3), "r"(b0), "r"(b1));
}

__device__ __forceinline__ uint32_t pack1(float x0, float x1)
{
    hf h0 = __float2half_rn(x0), h1 = __float2half_rn(x1);
    return ((uint32_t)__half_as_ushort(h1) << 16) | __half_as_ushort(h0);
}

__device__ __forceinline__ void cp16(uint32_t s, const void* g)
{
    asm volatile("cp.async.cg.shared.global [%0], [%1], 16;" :: "r"(s), "l"(g));
}
__device__ __forceinline__ void ldm_x4(uint32_t* r, uint32_t addr)
{
    asm volatile("ldmatrix.sync.aligned.m8n8.x4.shared.b16 {%0,%1,%2,%3}, [%4];"
        : "=r"(r[0]), "=r"(r[1]), "=r"(r[2]), "=r"(r[3]) : "r"(addr));
}

/* ---------------- merged weight transpose ---------------------------------- */
__global__ void __launch_bounds__(256) wt_all_kernel(
    const float* __restrict__ qkvw, const float* __restrict__ projw,
    const float* __restrict__ fc1w, const float* __restrict__ fc2w,
    hf* __restrict__ wq, hf* __restrict__ wp,
    hf* __restrict__ w1, hf* __restrict__ w2)
{
    int id = blockIdx.x;
    const float* W; hf* T; int K, N, tile;
    if (id < 1728)      { W = qkvw; T = wq; K = DIM;    N = 3*DIM;  tile = id; }
    else if (id < 2304) { W = projw; T = wp; K = DIM;   N = DIM;    tile = id - 1728; }
    else if (id < 4608) { W = fc1w; T = w1; K = DIM;    N = HIDDEN; tile = id - 2304; }
    else                { W = fc2w; T = w2; K = HIDDEN; N = DIM;    tile = id - 4608; }
    int nx = N >> 5;
    int n0 = (tile % nx) << 5, k0 = (tile / nx) << 5;

    __shared__ float s[32][33];
    int tx = threadIdx.x, ty = threadIdx.y;
    #pragma unroll
    for (int j = 0; j < 4; j++)
        s[ty + j*8][tx] = W[(long)(k0 + ty + j*8) * N + n0 + tx];
    __syncthreads();
    #pragma unroll
    for (int j = 0; j < 4; j++) {
        long o = (long)(n0 + ty + j*8) * K + k0 + tx;
        T[o] = __float2half_rn(s[tx][ty + j*8]);
    }
}

/* ---------------- layernorm -> single fp16 --------------------------------- */
__global__ void __launch_bounds__(256) ln_kernel(
    const float* __restrict__ x, const float* __restrict__ sc,
    const float* __restrict__ bi, hf* __restrict__ y)
{
    long row = blockIdx.x;
    int  t   = threadIdx.x;
    const float* xr = x + row * DIM;
    float v0 = xr[t], v1 = xr[t + 256], v2 = xr[t + 512];

    __shared__ float sbuf[8];
    __shared__ float s_mu, s_r;

    float s = v0 + v1 + v2;
    #pragma unroll
    for (int o = 16; o > 0; o >>= 1) s += __shfl_xor_sync(0xffffffffu, s, o);
    if ((t & 31) == 0) sbuf[t >> 5] = s;
    __syncthreads();
    if (t < 8) {
        float r = sbuf[t];
        #pragma unroll
        for (int o = 4; o > 0; o >>= 1) r += __shfl_xor_sync(0xffu, r, o);
        if (t == 0) s_mu = r * (1.0f / DIM);
    }
    __syncthreads();
    float mu = s_mu;
    float d0 = v0 - mu, d1 = v1 - mu, d2 = v2 - mu;
    float q = d0*d0 + d1*d1 + d2*d2;
    #pragma unroll
    for (int o = 16; o > 0; o >>= 1) q += __shfl_xor_sync(0xffffffffu, q, o);
    if ((t & 31) == 0) sbuf[t >> 5] = q;
    __syncthreads();
    if (t < 8) {
        float r = sbuf[t];
        #pragma unroll
        for (int o = 4; o > 0; o >>= 1) r += __shfl_xor_sync(0xffu, r, o);
        if (t == 0) s_r = rsqrtf(r * (1.0f / DIM) + LN_EPS);
    }
    __syncthreads();
    float rs = s_r;
    long base = row * DIM;
    y[base + t      ] = __float2half_rn(d0 * rs * sc[t      ] + bi[t      ]);
    y[base + t + 256] = __float2half_rn(d1 * rs * sc[t + 256] + bi[t + 256]);
    y[base + t + 512] = __float2half_rn(d2 * rs * sc[t + 512] + bi[t + 512]);
}

/* ================= flash attention: 4w x 32 q-rows, Q hoisted, exp2 (R15) == */
#define BQ  128
#define BKV 64
#define QST 72
#define SQ_ELE (BQ*QST)
#define SK_ELE (BKV*QST)
#define FA_SMEM ((SQ_ELE + 2*SK_ELE + SK_ELE) * 2)   /* 46080 B */

__global__ void __launch_bounds__(128, 2) flash_kernel(
    const hf* __restrict__ qkv, hf* __restrict__ att)
{
    extern __shared__ hf sm[];
    hf* Vs  = sm + SQ_ELE + 2*SK_ELE;
    uint32_t* VW = reinterpret_cast<uint32_t*>(Vs);
    uint32_t sQ, sK0, sV;
    {
        uint32_t base = (uint32_t)__cvta_generic_to_shared(sm);
        sQ = base; sK0 = base + SQ_ELE*2; sV = sK0 + 2*SK_ELE*2;
    }

    int t = threadIdx.x, lane = t & 31, wid = t >> 5;
    int gid = lane >> 2, tig = lane & 3;
    int t4 = lane >> 3, li = lane & 7;
    int a_row = (t4 & 1) * 8 + li,  a_col = (t4 >> 1) * 8;
    int b_row = (t4 >> 1) * 8 + li, b_col = (t4 & 1) * 8;

    int bh = blockIdx.y, b = bh / HEADS, h = bh % HEADS;
    int q0 = blockIdx.x * BQ;

    const hf* Qp = qkv + ((long)b * SEQ + q0) * (3*DIM) + h * HD;
    const hf* Kp = qkv + (long)b * SEQ * (3*DIM) + DIM     + h * HD;
    const hf* Vp = qkv + (long)b * SEQ * (3*DIM) + 2*DIM   + h * HD;

    auto issueQ = [&]() {
        #pragma unroll
        for (int i = 0; i < 8; i++) {
            int g = t + i * 128;
            int row = g >> 3, c = g & 7;
            cp16(sQ + (row*QST + c*8)*2, Qp + (long)row*(3*DIM) + c*8);
        }
    };
    auto issueK = [&](int it) {
        uint32_t kb = sK0 + (it & 1) * (SK_ELE*2);
        #pragma unroll
        for (int i = 0; i < 4; i++) {
            int g = t + i * 128;
            int row = g >> 3, c = g & 7;
            cp16(kb + (row*QST + c*8)*2, Kp + (long)(it*BKV + row)*(3*DIM) + c*8);
        }
        asm volatile("cp.async.commit_group;");
    };

    int vrp = t & 31, vdb = (t >> 5) * 16;
    uint32_t va[8], vb[8];
    auto loadV = [&](int it) {
        const hf* p0 = Vp + (long)(it * BKV + 2*vrp) * (3*DIM) + vdb;
        const hf* p1 = p0 + 3*DIM;
        uint4 a0 = *reinterpret_cast<const uint4*>(p0);
        uint4 a1 = *reinterpret_cast<const uint4*>(p0 + 8);
        uint4 b0 = *reinterpret_cast<const uint4*>(p1);
        uint4 b1 = *reinterpret_cast<const uint4*>(p1 + 8);
        va[0]=a0.x; va[1]=a0.y; va[2]=a0.z; va[3]=a0.w;
        va[4]=a1.x; va[5]=a1.y; va[6]=a1.z; va[7]=a1.w;
        vb[0]=b0.x; vb[1]=b0.y; vb[2]=b0.z; vb[3]=b0.w;
        vb[4]=b1.x; vb[5]=b1.y; vb[6]=b1.z; vb[7]=b1.w;
    };

    issueQ();
    issueK(0);
    loadV(0);

    asm volatile("cp.async.wait_group 0;");
    __syncthreads();
    int wm = wid * 32;
    uint32_t qf[4][2][4];
    #pragma unroll
    for (int ks = 0; ks < 4; ks++)
        #pragma unroll
        for (int tm = 0; tm < 2; tm++)
            ldm_x4(qf[ks][tm], sQ + ((wm + tm*16 + a_row)*QST + ks*16 + a_col)*2);

    float acc[2][8][4];
    float oacc[2][8][4];
    float mrow[2][2], lrow[2][2];
    #pragma unroll
    for (int i = 0; i < 2; i++) {
        mrow[i][0] = mrow[i][1] = -1e30f;
        lrow[i][0] = lrow[i][1] = 0.0f;
        #pragma unroll
        for (int j = 0; j < 8; j++)
            #pragma unroll
            for (int r = 0; r < 4; r++) oacc[i][j][r] = 0.0f;
    }

    for (int it = 0; it < SEQ / BKV; it++) {
        asm volatile("cp.async.wait_group 0;");
        __syncthreads();
        uint32_t sK = sK0 + (it & 1) * (SK_ELE*2);

        #pragma unroll
        for (int i = 0; i < 2; i++)
            #pragma unroll
            for (int j = 0; j < 8; j++)
                #pragma unroll
                for (int r = 0; r < 4; r++) acc[i][j][r] = 0.0f;

        #pragma unroll
        for (int ks = 0; ks < 4; ks++) {
            uint32_t kb4[4][4];
            #pragma unroll
            for (int p = 0; p < 4; p++)
                ldm_x4(kb4[p], sK + ((p*16 + b_row)*QST + ks*16 + b_col)*2);
            #pragma unroll
            for (int tn = 0; tn < 8; tn++) {
                uint32_t* kk = kb4[tn >> 1];
                uint32_t b0 = kk[(tn & 1) * 2], b1 = kk[(tn & 1) * 2 + 1];
                #pragma unroll
                for (int tm = 0; tm < 2; tm++) {
                    float* c = acc[tm][tn];
                    mma16816(c[0],c[1],c[2],c[3],
                             qf[ks][tm][0],qf[ks][tm][1],qf[ks][tm][2],qf[ks][tm][3],
                             b0,b1);
                }
            }
        }

        #pragma unroll
        for (int tm = 0; tm < 2; tm++) {
            float mx0 = -1e30f, mx1 = -1e30f;
            #pragma unroll
            for (int tn = 0; tn < 8; tn++) {
                float* c = acc[tm][tn];
                mx0 = fmaxf(mx0, fmaxf(c[0], c[1]));
                mx1 = fmaxf(mx1, fmaxf(c[2], c[3]));
            }
            #pragma unroll
            for (int o = 1; o <= 2; o <<= 1) {
                mx0 = fmaxf(mx0, __shfl_xor_sync(0xffffffffu, mx0, o));
                mx1 = fmaxf(mx1, __shfl_xor_sync(0xffffffffu, mx1, o));
            }
            float mn0 = fmaxf(mrow[tm][0], mx0);
            float mn1 = fmaxf(mrow[tm][1], mx1);
            float sc0 = exp2f((mrow[tm][0] - mn0) * S2LOG);
            float sc1 = exp2f((mrow[tm][1] - mn1) * S2LOG);
            float mb0 = mn0 * S2LOG;
            float mb1 = mn1 * S2LOG;
            float ls0 = 0.0f, ls1 = 0.0f;
            #pragma unroll
            for (int tn = 0; tn < 8; tn++) {
                float* c = acc[tm][tn];
                c[0] = exp2f(fmaf(c[0], S2LOG, -mb0));
                c[1] = exp2f(fmaf(c[1], S2LOG, -mb0));
                c[2] = exp2f(fmaf(c[2], S2LOG, -mb1));
                c[3] = exp2f(fmaf(c[3], S2LOG, -mb1));
                ls0 += c[0] + c[1];
                ls1 += c[2] + c[3];
            }
            #pragma unroll
            for (int o = 1; o <= 2; o <<= 1) {
                ls0 += __shfl_xor_sync(0xffffffffu, ls0, o);
                ls1 += __shfl_xor_sync(0xffffffffu, ls1, o);
            }
            lrow[tm][0] = lrow[tm][0] * sc0 + ls0;
            lrow[tm][1] = lrow[tm][1] * sc1 + ls1;
            mrow[tm][0] = mn0;
            mrow[tm][1] = mn1;
            #pragma unroll
            for (int to = 0; to < 8; to++) {
                oacc[tm][to][0] *= sc0; oacc[tm][to][1] *= sc0;
                oacc[tm][to][2] *= sc1; oacc[tm][to][3] *= sc1;
            }
        }

        #pragma unroll
        for (int k = 0; k < 8; k++) {
            VW[(vdb + 2*k    ) * (QST/2) + vrp] = __byte_perm(va[k], vb[k], 0x5410);
            VW[(vdb + 2*k + 1) * (QST/2) + vrp] = __byte_perm(va[k], vb[k], 0x7632);
        }
        if (it + 1 < SEQ / BKV) {
            issueK(it + 1);
            loadV(it + 1);
        }
        __syncthreads();

        #pragma unroll
        for (int j = 0; j < 4; j++) {
            uint32_t pH[2][4];
            #pragma unroll
            for (int tm = 0; tm < 2; tm++) {
                pH[tm][0] = pack1(acc[tm][2*j  ][0], acc[tm][2*j  ][1]);
                pH[tm][1] = pack1(acc[tm][2*j  ][2], acc[tm][2*j  ][3]);
                pH[tm][2] = pack1(acc[tm][2*j+1][0], acc[tm][2*j+1][1]);
                pH[tm][3] = pack1(acc[tm][2*j+1][2], acc[tm][2*j+1][3]);
            }
            uint32_t vb4[4][4];
            #pragma unroll
            for (int p = 0; p < 4; p++)
                ldm_x4(vb4[p], sV + ((p*16 + b_row)*QST + j*16 + b_col)*2);
            #pragma unroll
            for (int to = 0; to < 8; to++) {
                uint32_t* vv = vb4[to >> 1];
                uint32_t b0 = vv[(to & 1) * 2], b1 = vv[(to & 1) * 2 + 1];
                #pragma unroll
                for (int tm = 0; tm < 2; tm++) {
                    float* c = oacc[tm][to];
                    mma16816(c[0],c[1],c[2],c[3],
                             pH[tm][0],pH[tm][1],pH[tm][2],pH[tm][3], b0,b1);
                }
            }
        }
    }

    uint32_t* AW = reinterpret_cast<uint32_t*>(att);
    #pragma unroll
    for (int tm = 0; tm < 2; tm++) {
        float inv0 = 1.0f / lrow[tm][0];
        float inv1 = 1.0f / lrow[tm][1];
        int row = q0 + wm + tm*16 + gid;
        #pragma unroll
        for (int to = 0; to < 8; to++) {
            int col = h*HD + to*8 + tig*2;
            float* c = oacc[tm][to];
            long o0 = (((long)b*SEQ + row    ) * DIM + col) >> 1;
            long o1 = (((long)b*SEQ + row + 8) * DIM + col) >> 1;
            AW[o0] = pack1(c[0]*inv0, c[1]*inv0);
            AW[o1] = pack1(c[2]*inv1, c[3]*inv1);
        }
    }
}

/* ================= dense GEMM: fp16, BK=64, 2-stage, single barrier ========
 * The bottom barrier is provably redundant: issue(kk+1) runs only after the
 * top sync of iteration kk, which all threads reach only after finishing
 * compute of kk-1 on the buffer being overwritten. Bit-identical math.
 */
#define BN   128
#define BK2  64
#define SEB2 72

template <int BMT>
__global__ void __launch_bounds__(BMT*2, (BMT==128)?2:3) gemm_hf(
    const hf* __restrict__ Ag, const hf* __restrict__ Bg,
    const float* __restrict__ bias, const float* __restrict__ Rsd,
    float* __restrict__ Cf, hf* __restrict__ Ch, int doGelu,
    int M, int N, int K)
{
    constexpr int TSZA = BMT * SEB2;
    constexpr int TSZB = BN  * SEB2;
    extern __shared__ hf gsm[];
    uint32_t sbase = (uint32_t)__cvta_generic_to_shared(gsm);

    int m0 = blockIdx.y * BMT;
    int n0 = blockIdx.x * BN;
    int t  = threadIdx.x;
    int lane = t & 31, wid = t >> 5;
    int gid = lane >> 2, tig = lane & 3;
    int warp_m = (BMT == 128) ? ((wid >> 2) << 6) : 0;
    int warp_n = (wid & 3) << 5;

    int lrow = t >> 3, lcol = (t & 7) * 8;

    auto issue = [&](int st) {
        int buf = st & 1;
        long k0 = (long)st * BK2;
        uint32_t dA = sbase + (buf*TSZA)*2;
        uint32_t dB = sbase + (2*TSZA + buf*TSZB)*2;
        #pragma unroll
        for (int i = 0; i < 4; i++) {
            int row = lrow + i * (BMT/4);
            cp16(dA + (row*SEB2 + lcol)*2, Ag + (long)(m0 + row)*K + k0 + lcol);
        }
        #pragma unroll
        for (int i = 0; i < (BMT==128 ? 4 : 8); i++) {
            int row = lrow + i * (BMT==128 ? 32 : 16);
            cp16(dB + (row*SEB2 + lcol)*2, Bg + (long)(n0 + row)*K + k0 + lcol);
        }
        asm volatile("cp.async.commit_group;");
    };

    float acc[4][4][4];
    #pragma unroll
    for (int i = 0; i < 4; i++)
        #pragma unroll
        for (int j = 0; j < 4; j++)
            #pragma unroll
            for (int r = 0; r < 4; r++) acc[i][j][r] = 0.0f;

    int t4 = lane >> 3, li = lane & 7;
    int a_row = (t4 & 1) * 8 + li,  a_col = (t4 >> 1) * 8;
    int b_row = (t4 >> 1) * 8 + li, b_col = (t4 & 1) * 8;

    int kt = K / BK2;
    issue(0);

    for (int kk = 0; kk < kt; kk++) {
        asm volatile("cp.async.wait_group 0;");
        __syncthreads();
        if (kk + 1 < kt) issue(kk + 1);

        int buf = kk & 1;
        uint32_t sA = sbase + (buf*TSZA)*2;
        uint32_t sB = sbase + (2*TSZA + buf*TSZB)*2;

        #pragma unroll
        for (int ks = 0; ks < 4; ks++) {
            int kc = ks * 16;
            uint32_t a[4][4], bb2[2][4];
            #pragma unroll
            for (int tm = 0; tm < 4; tm++)
                ldm_x4(a[tm], sA + ((warp_m + tm*16 + a_row)*SEB2 + kc + a_col)*2);
            #pragma unroll
            for (int p = 0; p < 2; p++)
                ldm_x4(bb2[p], sB + ((warp_n + p*16 + b_row)*SEB2 + kc + b_col)*2);

            #pragma unroll
            for (int tm = 0; tm < 4; tm++)
                #pragma unroll
                for (int tn = 0; tn < 4; tn++) {
                    float* c = acc[tm][tn];
                    uint32_t* bb = bb2[tn >> 1];
                    mma16816(c[0],c[1],c[2],c[3],
                             a[tm][0],a[tm][1],a[tm][2],a[tm][3],
                             bb[(tn&1)*2], bb[(tn&1)*2+1]);
                }
        }
        /* no bottom barrier: top wait+sync of the next iteration covers it */
    }

    #pragma unroll
    for (int tn = 0; tn < 4; tn++) {
        int col = n0 + warp_n + tn * 8 + tig * 2;
        float b0 = bias ? bias[col]     : 0.0f;
        float b1 = bias ? bias[col + 1] : 0.0f;
        #pragma unroll
        for (int tm = 0; tm < 4; tm++) {
            int row0 = m0 + warp_m + tm * 16 + gid;
            float* c = acc[tm][tn];
            #pragma unroll
            for (int half = 0; half < 2; half++) {
                int row = row0 + half * 8;
                float v0 = c[half*2 + 0] + b0;
                float v1 = c[half*2 + 1] + b1;
                long off = (long)row * N + col;
                if (Ch) {
                    if (doGelu) { v0 = gelu_fast(v0); v1 = gelu_fast(v1); }
                    reinterpret_cast<uint32_t*>(Ch)[off >> 1] = pack1(v0, v1);
                } else {
                    if (Rsd) {
                        float2 r = *reinterpret_cast<const float2*>(Rsd + off);
                        v0 += r.x; v1 += r.y;
                    }
                    *reinterpret_cast<float2*>(Cf + off) = make_float2(v0, v1);
                }
            }
        }
    }
}

#define GEMM_SMEM_128 (2*(128+128)*SEB2*2)   /* 73728 */
#define GEMM_SMEM_64  (2*( 64+128)*SEB2*2)   /* 55296 */

/* ---------------- launch --------------------------------------------------- */
extern "C" void kernel_launch(void* const* d_in, const int* in_sizes, int n_in,
                              void* d_out, int out_size)
{
    const float* x     = (const float*)d_in[0];
    const float* ln1s  = (const float*)d_in[1];
    const float* ln1b  = (const float*)d_in[2];
    const float* qkvw  = (const float*)d_in[3];
    const float* qkvb  = (const float*)d_in[4];
    const float* projw = (const float*)d_in[5];
    const float* projb = (const float*)d_in[6];
    const float* ln2s  = (const float*)d_in[7];
    const float* ln2b  = (const float*)d_in[8];
    const float* fc1w  = (const float*)d_in[9];
    const float* fc1b  = (const float*)d_in[10];
    const float* fc2w  = (const float*)d_in[11];
    const float* fc2b  = (const float*)d_in[12];
    float* out = (float*)d_out;

    hf *y, *qkvh, *att, *hb, *wq, *wp, *w1, *w2;
    float *x1;
    cudaGetSymbolAddress((void**)&y,    g_y);
    cudaGetSymbolAddress((void**)&qkvh, g_qkv);
    cudaGetSymbolAddress((void**)&att,  g_att);
    cudaGetSymbolAddress((void**)&x1,   g_x1);
    cudaGetSymbolAddress((void**)&hb,   g_h);
    cudaGetSymbolAddress((void**)&wq,   g_wq);
    cudaGetSymbolAddress((void**)&wp,   g_wp);
    cudaGetSymbolAddress((void**)&w1,   g_w1);
    cudaGetSymbolAddress((void**)&w2,   g_w2);

    cudaFuncSetAttribute(flash_kernel,
        cudaFuncAttributeMaxDynamicSharedMemorySize, FA_SMEM);
    cudaFuncSetAttribute(gemm_hf<128>,
        cudaFuncAttributeMaxDynamicSharedMemorySize, GEMM_SMEM_128);
    cudaFuncSetAttribute(gemm_hf<64>,
        cudaFuncAttributeMaxDynamicSharedMemorySize, GEMM_SMEM_64);

    /* 0. all weight transposes, one launch */
    wt_all_kernel<<<6912, dim3(32,8)>>>(qkvw, projw, fc1w, fc2w, wq, wp, w1, w2);

    /* 1. LN1 -> y fp16 */
    ln_kernel<<<ROWS, 256>>>(x, ln1s, ln1b, y);

    /* 2. QKV = y @ Wq + b  (fp16 out) */
    gemm_hf<128><<<dim3(3*DIM/BN, ROWS/128), 256, GEMM_SMEM_128>>>(
        y, wq, qkvb, nullptr, nullptr, qkvh, 0,
        ROWS, 3*DIM, DIM);

    /* 3-5. flash attention -> att fp16 */
    flash_kernel<<<dim3(SEQ / BQ, BATCH * HEADS), 128, FA_SMEM>>>(qkvh, att);

    /* 6. x1 = att @ Wp + b + x  (f32 out) */
    gemm_hf<64><<<dim3(DIM/BN, ROWS/64), 128, GEMM_SMEM_64>>>(
        att, wp, projb, x, x1, nullptr, 0,
        ROWS, DIM, DIM);

    /* 7. LN2 -> y fp16 */
    ln_kernel<<<ROWS, 256>>>(x1, ln2s, ln2b, y);

    /* 8. h = gelu(y @ W1 + b)  (fp16 out) */
    gemm_hf<128><<<dim3(HIDDEN/BN, ROWS/128), 256, GEMM_SMEM_128>>>(
        y, w1, fc1b, nullptr, nullptr, hb, 1,
        ROWS, HIDDEN, DIM);

    /* 9. out = h @ W2 + b + x1  (f32 out) */
    gemm_hf<64><<<dim3(DIM/BN, ROWS/64), 128, GEMM_SMEM_64>>>(
        hb, w2, fc2b, x1, out, nullptr, 0,
        ROWS, DIM, HIDDEN);
}